// round 6
// baseline (speedup 1.0000x reference)
#include <cuda_runtime.h>
#include <math.h>

#define B_ROWS 16384
#define D_COLS 4096
#define H1N 64
#define H2N 32
#define BD_TOT (16384.0*4096.0)

typedef unsigned long long u64;
typedef unsigned int u32;

// ---------------- scratch (device globals, no allocations) ----------------
__device__ float  d_srow[B_ROWS];
__device__ float  d_med;
__device__ double d_nsum[2];                 // sum(norm), sum(norm^2)
__device__ float  d_G[B_ROWS * H1N];         // norm_raw @ W_in
__device__ double d_s1[H1N], d_q1[H1N];      // col stats of G
__device__ float  d_H2[B_ROWS * H2N];        // h1 @ W_enc + b_enc
__device__ double d_s2[H2N], d_q2[H2N];
__device__ float  d_H3[B_ROWS * H1N];        // h2 @ W_dec + b_dec
__device__ double d_s3[H1N], d_q3[H1N];

// ---------------- tf32 mma helpers -----------------------------------------
__device__ __forceinline__ u32 to_tf32(float f) {
    u32 u; asm("cvt.rna.tf32.f32 %0, %1;" : "=r"(u) : "f"(f)); return u;
}
__device__ __forceinline__ void mma1688(float c[4], const u32 a[4], const u32 b[2]) {
    asm volatile(
        "mma.sync.aligned.m16n8k8.row.col.f32.tf32.tf32.f32 "
        "{%0,%1,%2,%3},{%4,%5,%6,%7},{%8,%9},{%0,%1,%2,%3};"
        : "+f"(c[0]), "+f"(c[1]), "+f"(c[2]), "+f"(c[3])
        : "r"(a[0]), "r"(a[1]), "r"(a[2]), "r"(a[3]), "r"(b[0]), "r"(b[1]));
}
__device__ __forceinline__ float fast_sigmoid(float z) {
    return __fdividef(1.f, 1.f + __expf(-z));
}

// ---------------- K0: zero the accumulators --------------------------------
__global__ void k_zero() {
    int t = threadIdx.x;
    if (t < 2)   d_nsum[t] = 0.0;
    if (t < H1N) { d_s1[t] = 0.0; d_q1[t] = 0.0; d_s3[t] = 0.0; d_q3[t] = 0.0; }
    if (t < H2N) { d_s2[t] = 0.0; d_q2[t] = 0.0; }
}

// ---------------- K1: per-row sums of x ------------------------------------
__global__ __launch_bounds__(256) void k_rowsum(const float* __restrict__ x) {
    int b = blockIdx.x;
    const float4* row = (const float4*)(x + (size_t)b * D_COLS);
    float s = 0.f;
#pragma unroll
    for (int i = 0; i < 4; i++) {
        float4 v = row[threadIdx.x + i * 256];
        s += (v.x + v.y) + (v.z + v.w);
    }
#pragma unroll
    for (int o = 16; o > 0; o >>= 1) s += __shfl_down_sync(0xffffffffu, s, o);
    __shared__ float ws[8];
    if ((threadIdx.x & 31) == 0) ws[threadIdx.x >> 5] = s;
    __syncthreads();
    if (threadIdx.x == 0) {
        float t = 0.f;
#pragma unroll
        for (int i = 0; i < 8; i++) t += ws[i];
        d_srow[b] = t;
    }
}

// ---------------- K2: lower median via 32-pass radix select ----------------
__global__ void k_median() {
    extern __shared__ u32 keys[];   // 16384 keys = 64 KB (dynamic)
    __shared__ int cnt;
    int tid = threadIdx.x;
    for (int i = tid; i < B_ROWS; i += 1024) {
        u32 u = __float_as_uint(d_srow[i]);
        keys[i] = (u & 0x80000000u) ? ~u : (u | 0x80000000u);  // order-preserving
    }
    __syncthreads();

    u32 prefix = 0;
    int k = (B_ROWS - 1) / 2;      // 8191 : lower median rank (0-based)
    for (int bit = 31; bit >= 0; --bit) {
        u32 bmask = 1u << bit;
        u32 hmask = ~((bmask << 1) - 1u);   // determined high bits (0 when bit==31)
        if (tid == 0) cnt = 0;
        __syncthreads();
        int local = 0;
        for (int i = tid; i < B_ROWS; i += 1024) {
            u32 kv = keys[i];
            if ((((kv ^ prefix) & hmask) == 0) && !(kv & bmask)) local++;
        }
        atomicAdd(&cnt, local);
        __syncthreads();
        int c0 = cnt;
        if (k >= c0) { prefix |= bmask; k -= c0; }
        __syncthreads();
    }
    if (tid == 0) {
        u32 u = (prefix & 0x80000000u) ? (prefix & 0x7FFFFFFFu) : ~prefix;
        d_med = __uint_as_float(u);
    }
}

// ---------------- K3: fused norm + GEMM1 (3xTF32 MMA) + global stats -------
// BM=64 rows/block, N=64, K chunks of 32. 256 threads = 8 warps: 4(M)x2(N).
#define G1_ALD 36
#define G1_WLD 72
__global__ __launch_bounds__(256) void k_gemm1(const float* __restrict__ x,
                                               const float* __restrict__ Win) {
    __shared__ float rfac[64];
    __shared__ u32 Ahi[64 * G1_ALD], Alo[64 * G1_ALD];   // [row][k]
    __shared__ u32 Whi[32 * G1_WLD], Wlo[32 * G1_WLD];   // [k][col]
    __shared__ double red[512];
    int tid = threadIdx.x;
    int r0  = blockIdx.x * 64;
    if (tid < 64) rfac[tid] = d_med / d_srow[r0 + tid];
    __syncthreads();

    int warp = tid >> 5, lane = tid & 31;
    int wm = warp >> 1, wn = warp & 1;
    int g = lane >> 2, t = lane & 3;
    int lrow = tid >> 2, lk = (tid & 3) * 8;     // A loader: 4 thr/row, 8 k each
    int wrow = tid >> 3, wcol = (tid & 7) * 8;   // W loader: 8 thr/row, 8 cols each
    float rf = rfac[lrow];

    float cfr[4][4];
#pragma unroll
    for (int nt = 0; nt < 4; nt++)
#pragma unroll
        for (int i = 0; i < 4; i++) cfr[nt][i] = 0.f;
    double dsum = 0.0, dsq = 0.0;

    for (int kk = 0; kk < D_COLS; kk += 32) {
        // ---- load x chunk, norm on the fly, split tf32 hi/lo, stats ----
        {
            const float* xp = x + (size_t)(r0 + lrow) * D_COLS + kk + lk;
            float n[8];
            float4 v0 = *(const float4*)(xp);
            float4 v1 = *(const float4*)(xp + 4);
            n[0] = __logf(fmaf(v0.x, rf, 1.f)); n[1] = __logf(fmaf(v0.y, rf, 1.f));
            n[2] = __logf(fmaf(v0.z, rf, 1.f)); n[3] = __logf(fmaf(v0.w, rf, 1.f));
            n[4] = __logf(fmaf(v1.x, rf, 1.f)); n[5] = __logf(fmaf(v1.y, rf, 1.f));
            n[6] = __logf(fmaf(v1.z, rf, 1.f)); n[7] = __logf(fmaf(v1.w, rf, 1.f));
            float ls = 0.f, lq = 0.f;
            u32* ah = Ahi + lrow * G1_ALD + lk;
            u32* al = Alo + lrow * G1_ALD + lk;
#pragma unroll
            for (int j = 0; j < 8; j++) {
                ls += n[j]; lq = fmaf(n[j], n[j], lq);
                u32 hb = to_tf32(n[j]);
                float hf = __uint_as_float(hb);
                ah[j] = hb;
                al[j] = to_tf32(n[j] - hf);
            }
            dsum += (double)ls; dsq += (double)lq;
        }
        // ---- load W chunk (32 x 64), split tf32 ----
        {
            const float* wp = Win + (size_t)(kk + wrow) * 64 + wcol;
            float4 v0 = *(const float4*)(wp);
            float4 v1 = *(const float4*)(wp + 4);
            float wv[8] = {v0.x, v0.y, v0.z, v0.w, v1.x, v1.y, v1.z, v1.w};
            u32* wh = Whi + wrow * G1_WLD + wcol;
            u32* wl = Wlo + wrow * G1_WLD + wcol;
#pragma unroll
            for (int j = 0; j < 8; j++) {
                u32 hb = to_tf32(wv[j]);
                float hf = __uint_as_float(hb);
                wh[j] = hb;
                wl[j] = to_tf32(wv[j] - hf);
            }
        }
        __syncthreads();
        // ---- mma: 4 k-steps of 8 ----
        int arow0 = wm * 16 + g;
#pragma unroll
        for (int kt = 0; kt < 4; kt++) {
            int k0 = kt * 8;
            u32 ah[4], al[4];
            ah[0] = Ahi[arow0 * G1_ALD + k0 + t];
            ah[1] = Ahi[(arow0 + 8) * G1_ALD + k0 + t];
            ah[2] = Ahi[arow0 * G1_ALD + k0 + t + 4];
            ah[3] = Ahi[(arow0 + 8) * G1_ALD + k0 + t + 4];
            al[0] = Alo[arow0 * G1_ALD + k0 + t];
            al[1] = Alo[(arow0 + 8) * G1_ALD + k0 + t];
            al[2] = Alo[arow0 * G1_ALD + k0 + t + 4];
            al[3] = Alo[(arow0 + 8) * G1_ALD + k0 + t + 4];
#pragma unroll
            for (int nt = 0; nt < 4; nt++) {
                int bc = wn * 32 + nt * 8 + g;
                u32 bh[2] = { Whi[(k0 + t) * G1_WLD + bc], Whi[(k0 + t + 4) * G1_WLD + bc] };
                u32 bl[2] = { Wlo[(k0 + t) * G1_WLD + bc], Wlo[(k0 + t + 4) * G1_WLD + bc] };
                mma1688(cfr[nt], ah, bh);
                mma1688(cfr[nt], al, bh);
                mma1688(cfr[nt], ah, bl);
            }
        }
        __syncthreads();
    }
    // ---- writeback G ----
#pragma unroll
    for (int nt = 0; nt < 4; nt++) {
        int col = wn * 32 + nt * 8 + t * 2;
        int rA = r0 + wm * 16 + g, rB = rA + 8;
        *(float2*)&d_G[(size_t)rA * 64 + col] = make_float2(cfr[nt][0], cfr[nt][1]);
        *(float2*)&d_G[(size_t)rB * 64 + col] = make_float2(cfr[nt][2], cfr[nt][3]);
    }
    // ---- global norm stats reduction ----
    red[tid] = dsum; red[256 + tid] = dsq;
    __syncthreads();
    for (int s = 128; s > 0; s >>= 1) {
        if (tid < s) { red[tid] += red[tid + s]; red[256 + tid] += red[256 + tid + s]; }
        __syncthreads();
    }
    if (tid == 0) {
        atomicAdd(&d_nsum[0], red[0]);
        atomicAdd(&d_nsum[1], red[256]);
    }
}

// ---------------- K4: column stats of G ------------------------------------
__global__ __launch_bounds__(256) void k_colstatsG() {
    int col = threadIdx.x & 63, rg = threadIdx.x >> 6;
    int r0 = blockIdx.x * 256;
    double s = 0.0, q = 0.0;
    for (int r = rg; r < 256; r += 4) {
        float v = d_G[(size_t)(r0 + r) * 64 + col];
        s += (double)v; q += (double)v * (double)v;
    }
    __shared__ double sh[256], shq[256];
    sh[threadIdx.x] = s; shq[threadIdx.x] = q;
    __syncthreads();
    if (rg == 0) {
#pragma unroll
        for (int g = 1; g < 4; g++) { s += sh[col + 64 * g]; q += shq[col + 64 * g]; }
        atomicAdd(&d_s1[col], s);
        atomicAdd(&d_q1[col], q);
    }
}

// ---------------- K5: layer-1 BN+ReLU -> h1 @ W_enc + b_enc (+stats) -------
__global__ __launch_bounds__(256) void k_mlp2(const float* __restrict__ g1,
                                              const float* __restrict__ bt1,
                                              const float* __restrict__ Wenc,
                                              const float* __restrict__ benc) {
    __shared__ float mu1[64], sc1[64], bts[64];
    __shared__ float We[64 * 32];
    __shared__ float be[32];
    __shared__ float h1buf[8][64];
    int tid = threadIdx.x;
    if (tid < 64) {
        double tot = d_nsum[0], totq = d_nsum[1];
        double sigma2 = (totq - tot * tot / BD_TOT) / (BD_TOT - 1.0);
        double mu  = d_s1[tid] / 16384.0;
        double var = d_q1[tid] / 16384.0 - mu * mu;
        mu1[tid] = (float)mu;
        sc1[tid] = g1[tid] * (float)rsqrt(var + 1e-5 * sigma2);
        bts[tid] = bt1[tid];
    }
    for (int i = tid; i < 64 * 32; i += 256) We[i] = Wenc[i];
    if (tid < 32) be[tid] = benc[tid];
    __syncthreads();

    int w = tid >> 5, lane = tid & 31;
    int rbase = blockIdx.x * 64 + w * 8;
    float ls = 0.f, lq = 0.f;
    for (int rr = 0; rr < 8; rr++) {
        int row = rbase + rr;
        float a0 = d_G[(size_t)row * 64 + lane];
        float a1 = d_G[(size_t)row * 64 + 32 + lane];
        h1buf[w][lane]      = fmaxf(fmaf(a0 - mu1[lane],      sc1[lane],      bts[lane]),      0.f);
        h1buf[w][32 + lane] = fmaxf(fmaf(a1 - mu1[32 + lane], sc1[32 + lane], bts[32 + lane]), 0.f);
        __syncwarp();
        float acc = be[lane];
#pragma unroll
        for (int k = 0; k < 64; k++) acc = fmaf(h1buf[w][k], We[k * 32 + lane], acc);
        d_H2[(size_t)row * 32 + lane] = acc;
        ls += acc; lq += acc * acc;
        __syncwarp();
    }
    atomicAdd(&d_s2[lane], (double)ls);
    atomicAdd(&d_q2[lane], (double)lq);
}

// ---------------- K6: layer-2 BN+ReLU -> h2 @ W_dec + b_dec (+stats) -------
__global__ __launch_bounds__(256) void k_mlp3(const float* __restrict__ g2,
                                              const float* __restrict__ bt2,
                                              const float* __restrict__ Wdec,
                                              const float* __restrict__ bdec) {
    __shared__ float mu2[32], sc2[32], bts[32];
    __shared__ float Wd[32 * 64];
    __shared__ float bd[64];
    __shared__ float h2buf[8][32];
    int tid = threadIdx.x;
    if (tid < 32) {
        double mu  = d_s2[tid] / 16384.0;
        double var = d_q2[tid] / 16384.0 - mu * mu;
        mu2[tid] = (float)mu;
        sc2[tid] = g2[tid] * (float)rsqrt(var + 1e-5);
        bts[tid] = bt2[tid];
    }
    for (int i = tid; i < 32 * 64; i += 256) Wd[i] = Wdec[i];
    if (tid < 64) bd[tid] = bdec[tid];
    __syncthreads();

    int w = tid >> 5, lane = tid & 31;
    int rbase = blockIdx.x * 64 + w * 8;
    float ls0 = 0.f, lq0 = 0.f, ls1 = 0.f, lq1 = 0.f;
    for (int rr = 0; rr < 8; rr++) {
        int row = rbase + rr;
        float v = d_H2[(size_t)row * 32 + lane];
        h2buf[w][lane] = fmaxf(fmaf(v - mu2[lane], sc2[lane], bts[lane]), 0.f);
        __syncwarp();
        float acc0 = bd[lane], acc1 = bd[32 + lane];
#pragma unroll
        for (int k = 0; k < 32; k++) {
            float h = h2buf[w][k];
            acc0 = fmaf(h, Wd[k * 64 + lane],      acc0);
            acc1 = fmaf(h, Wd[k * 64 + 32 + lane], acc1);
        }
        d_H3[(size_t)row * 64 + lane]      = acc0;
        d_H3[(size_t)row * 64 + 32 + lane] = acc1;
        ls0 += acc0; lq0 += acc0 * acc0;
        ls1 += acc1; lq1 += acc1 * acc1;
        __syncwarp();
    }
    atomicAdd(&d_s3[lane],      (double)ls0);
    atomicAdd(&d_q3[lane],      (double)lq0);
    atomicAdd(&d_s3[32 + lane], (double)ls1);
    atomicAdd(&d_q3[32 + lane], (double)lq1);
}

// ---------------- K7: BN3+ReLU -> h3 @ {W_pi,W_m,W_th} + act (tf32 MMA) ----
// BM=128 x BN=128 tile, K=64 resident. 8 warps: 4(M) x 2(N).
// W smem columns permuted within 16-col groups so C fragments of tile pairs
// form 4 contiguous global columns -> float4 stores.
#define AH_LD 68
#define WS_LD 136
__global__ __launch_bounds__(256, 2) void k_out(const float* __restrict__ g3,
                                                const float* __restrict__ bt3,
                                                const float* __restrict__ Wpi,
                                                const float* __restrict__ bpi,
                                                const float* __restrict__ Wm,
                                                const float* __restrict__ bm,
                                                const float* __restrict__ Wth,
                                                const float* __restrict__ bth,
                                                float* __restrict__ out) {
    extern __shared__ u32 smu[];
    u32*   Ah  = smu;                       // 128 x 68
    u32*   Wsm = smu + 128 * AH_LD;         // 64 x 136 (column-permuted)
    float* mu3 = (float*)(smu + 128 * AH_LD + 64 * WS_LD);
    float* sc3 = mu3 + 64;
    float* bts = sc3 + 64;
    float* bs  = bts + 64;                  // 128 (natural global-col order)

    int tid = threadIdx.x;
    int mz  = blockIdx.z;
    const float* W  = (mz == 0) ? Wpi : ((mz == 1) ? Wm : Wth);
    const float* bb = (mz == 0) ? bpi : ((mz == 1) ? bm : bth);
    int c0 = blockIdx.x * 128, r0 = blockIdx.y * 128;

    if (tid < 64) {
        double mu  = d_s3[tid] / 16384.0;
        double var = d_q3[tid] / 16384.0 - mu * mu;
        mu3[tid] = (float)mu;
        sc3[tid] = g3[tid] * (float)rsqrt(var + 1e-5);
        bts[tid] = bt3[tid];
    }
    if (tid < 128) bs[tid] = bb[c0 + tid];
    __syncthreads();

    {   // load h3 tile 128x64 (BN+ReLU+tf32)
        int lr = tid >> 1, cb = (tid & 1) * 32;
        const float4* src = (const float4*)&d_H3[(size_t)(r0 + lr) * 64 + cb];
        u32* dst = Ah + lr * AH_LD + cb;
#pragma unroll
        for (int j = 0; j < 8; j++) {
            float4 v = src[j];
            int c = cb + j * 4;
            uint4 o;
            o.x = to_tf32(fmaxf(fmaf(v.x - mu3[c + 0], sc3[c + 0], bts[c + 0]), 0.f));
            o.y = to_tf32(fmaxf(fmaf(v.y - mu3[c + 1], sc3[c + 1], bts[c + 1]), 0.f));
            o.z = to_tf32(fmaxf(fmaf(v.z - mu3[c + 2], sc3[c + 2], bts[c + 2]), 0.f));
            o.w = to_tf32(fmaxf(fmaf(v.w - mu3[c + 3], sc3[c + 3], bts[c + 3]), 0.f));
            *(uint4*)(dst + j * 4) = o;
        }
        // load W tile 64x128 (tf32) with column permutation:
        // global cols [4q,4q+3] of 16-group -> smem cols {2q,2q+1} and {8+2q,8+2q+1}
        int kr = tid >> 2, wb = (tid & 3) * 32;
        const float* wsrc = &W[(size_t)kr * 4096 + c0 + wb];
        u32* wrow = Wsm + kr * WS_LD;
#pragma unroll
        for (int j = 0; j < 8; j++) {
            float4 v = *(const float4*)(wsrc + j * 4);
            int gc = wb + j * 4;              // global col of v.x (within 128 tile)
            int grp = gc >> 4, q = (gc & 15) >> 2;
            u32* base = wrow + grp * 16;
            uint2 loxy = make_uint2(to_tf32(v.x), to_tf32(v.y));
            uint2 lozw = make_uint2(to_tf32(v.z), to_tf32(v.w));
            *(uint2*)(base + 2 * q)     = loxy;
            *(uint2*)(base + 8 + 2 * q) = lozw;
        }
    }
    __syncthreads();

    int warp = tid >> 5, lane = tid & 31;
    int wm = warp >> 1, wn = warp & 1;
    int g = lane >> 2, t = lane & 3;
    int arow0 = wm * 32 + g;
    int bcol0 = wn * 64 + g;

    float cfr[2][8][4];
#pragma unroll
    for (int mt = 0; mt < 2; mt++)
#pragma unroll
        for (int nt = 0; nt < 8; nt++)
#pragma unroll
            for (int i = 0; i < 4; i++) cfr[mt][nt][i] = 0.f;

#pragma unroll
    for (int kt = 0; kt < 8; kt++) {
        int k0 = kt * 8;
        u32 bfr[8][2];
#pragma unroll
        for (int nt = 0; nt < 8; nt++) {
            bfr[nt][0] = Wsm[(k0 + t) * WS_LD + bcol0 + nt * 8];
            bfr[nt][1] = Wsm[(k0 + t + 4) * WS_LD + bcol0 + nt * 8];
        }
        u32 afr[2][4];
#pragma unroll
        for (int mt = 0; mt < 2; mt++) {
            int r = arow0 + mt * 16;
            afr[mt][0] = Ah[r * AH_LD + k0 + t];
            afr[mt][1] = Ah[(r + 8) * AH_LD + k0 + t];
            afr[mt][2] = Ah[r * AH_LD + k0 + t + 4];
            afr[mt][3] = Ah[(r + 8) * AH_LD + k0 + t + 4];
        }
#pragma unroll
        for (int mt = 0; mt < 2; mt++)
#pragma unroll
            for (int nt = 0; nt < 8; nt++)
                mma1688(cfr[mt][nt], afr[mt], bfr[nt]);
    }

    size_t obase = (size_t)mz * (size_t)B_ROWS * D_COLS + (size_t)r0 * D_COLS + c0;
#pragma unroll
    for (int mt = 0; mt < 2; mt++) {
        int rA = wm * 32 + mt * 16 + g;
        int rB = rA + 8;
#pragma unroll
        for (int p = 0; p < 4; p++) {        // tile pair (2p, 2p+1) -> 4 contiguous cols
            int gcb = wn * 64 + p * 16 + t * 4;
            float4 bv = *(float4*)&bs[gcb];
            float4 zA = make_float4(cfr[mt][2 * p][0] + bv.x, cfr[mt][2 * p][1] + bv.y,
                                    cfr[mt][2 * p + 1][0] + bv.z, cfr[mt][2 * p + 1][1] + bv.w);
            float4 zB = make_float4(cfr[mt][2 * p][2] + bv.x, cfr[mt][2 * p][3] + bv.y,
                                    cfr[mt][2 * p + 1][2] + bv.z, cfr[mt][2 * p + 1][3] + bv.w);
            if (mz == 0) {
                zA.x = fast_sigmoid(zA.x); zA.y = fast_sigmoid(zA.y);
                zA.z = fast_sigmoid(zA.z); zA.w = fast_sigmoid(zA.w);
                zB.x = fast_sigmoid(zB.x); zB.y = fast_sigmoid(zB.y);
                zB.z = fast_sigmoid(zB.z); zB.w = fast_sigmoid(zB.w);
            } else {
                zA.x = __expf(zA.x); zA.y = __expf(zA.y);
                zA.z = __expf(zA.z); zA.w = __expf(zA.w);
                zB.x = __expf(zB.x); zB.y = __expf(zB.y);
                zB.z = __expf(zB.z); zB.w = __expf(zB.w);
            }
            *(float4*)&out[obase + (size_t)rA * D_COLS + gcb] = zA;
            *(float4*)&out[obase + (size_t)rB * D_COLS + gcb] = zB;
        }
    }
}

// ---------------- launch ----------------------------------------------------
extern "C" void kernel_launch(void* const* d_in, const int* in_sizes, int n_in,
                              void* d_out, int out_size) {
    const float* x    = (const float*)d_in[0];
    const float* Win  = (const float*)d_in[1];
    const float* g1   = (const float*)d_in[3];
    const float* bt1  = (const float*)d_in[4];
    const float* Wenc = (const float*)d_in[5];
    const float* benc = (const float*)d_in[6];
    const float* g2   = (const float*)d_in[7];
    const float* bt2  = (const float*)d_in[8];
    const float* Wdec = (const float*)d_in[9];
    const float* bdec = (const float*)d_in[10];
    const float* g3   = (const float*)d_in[11];
    const float* bt3  = (const float*)d_in[12];
    const float* Wpi  = (const float*)d_in[13];
    const float* bpi  = (const float*)d_in[14];
    const float* Wm   = (const float*)d_in[15];
    const float* bm   = (const float*)d_in[16];
    const float* Wth  = (const float*)d_in[17];
    const float* bth  = (const float*)d_in[18];
    float* out = (float*)d_out;

    const int koutSmem = (128 * AH_LD + 64 * WS_LD) * 4 + (64 * 3 + 128) * 4;

    cudaFuncSetAttribute(k_median, cudaFuncAttributeMaxDynamicSharedMemorySize, 65536);
    cudaFuncSetAttribute(k_out,    cudaFuncAttributeMaxDynamicSharedMemorySize, koutSmem);

    k_zero<<<1, 64>>>();
    k_rowsum<<<B_ROWS, 256>>>(x);
    k_median<<<1, 1024, 65536>>>();
    k_gemm1<<<B_ROWS / 64, 256>>>(x, Win);
    k_colstatsG<<<64, 256>>>();
    k_mlp2<<<B_ROWS / 64, 256>>>(g1, bt1, Wenc, benc);
    k_mlp3<<<B_ROWS / 64, 256>>>(g2, bt2, Wdec, bdec);
    dim3 g(D_COLS / 128, B_ROWS / 128, 3);
    k_out<<<g, 256, koutSmem>>>(g3, bt3, Wpi, bpi, Wm, bm, Wth, bth, out);
}

// round 8
// speedup vs baseline: 1.2288x; 1.2288x over previous
#include <cuda_runtime.h>
#include <math.h>

#define B_ROWS 16384
#define D_COLS 4096
#define H1N 64
#define H2N 32
#define BD_TOT (16384.0*4096.0)
#define NSLAB 4
#define KSLAB 1024

typedef unsigned long long u64;
typedef unsigned int u32;

// ---------------- scratch (device globals, no allocations) ----------------
__device__ float  d_srow[B_ROWS];
__device__ float  d_med;
__device__ double d_nsum[2];                 // sum(norm), sum(norm^2)
__device__ float  d_Gp[NSLAB * B_ROWS * H1N]; // partial G per K-slab
__device__ float  d_G[B_ROWS * H1N];         // norm_raw @ W_in
__device__ double d_s1[H1N], d_q1[H1N];      // col stats of G
__device__ float  d_H2[B_ROWS * H2N];        // h1 @ W_enc + b_enc
__device__ double d_s2[H2N], d_q2[H2N];
__device__ float  d_H3[B_ROWS * H1N];        // h2 @ W_dec + b_dec
__device__ double d_s3[H1N], d_q3[H1N];

// ---------------- tf32 mma helpers -----------------------------------------
__device__ __forceinline__ u32 to_tf32(float f) {
    u32 u; asm("cvt.rna.tf32.f32 %0, %1;" : "=r"(u) : "f"(f)); return u;
}
__device__ __forceinline__ void mma1688(float c[4], const u32 a[4], const u32 b[2]) {
    asm volatile(
        "mma.sync.aligned.m16n8k8.row.col.f32.tf32.tf32.f32 "
        "{%0,%1,%2,%3},{%4,%5,%6,%7},{%8,%9},{%0,%1,%2,%3};"
        : "+f"(c[0]), "+f"(c[1]), "+f"(c[2]), "+f"(c[3])
        : "r"(a[0]), "r"(a[1]), "r"(a[2]), "r"(a[3]), "r"(b[0]), "r"(b[1]));
}
__device__ __forceinline__ float fast_sigmoid(float z) {
    return __fdividef(1.f, 1.f + __expf(-z));
}

// ---------------- K0: zero the accumulators --------------------------------
__global__ void k_zero() {
    int t = threadIdx.x;
    if (t < 2)   d_nsum[t] = 0.0;
    if (t < H1N) { d_s1[t] = 0.0; d_q1[t] = 0.0; d_s3[t] = 0.0; d_q3[t] = 0.0; }
    if (t < H2N) { d_s2[t] = 0.0; d_q2[t] = 0.0; }
}

// ---------------- K1: per-row sums of x ------------------------------------
__global__ __launch_bounds__(256) void k_rowsum(const float* __restrict__ x) {
    int b = blockIdx.x;
    const float4* row = (const float4*)(x + (size_t)b * D_COLS);
    float s = 0.f;
#pragma unroll
    for (int i = 0; i < 4; i++) {
        float4 v = row[threadIdx.x + i * 256];
        s += (v.x + v.y) + (v.z + v.w);
    }
#pragma unroll
    for (int o = 16; o > 0; o >>= 1) s += __shfl_down_sync(0xffffffffu, s, o);
    __shared__ float ws[8];
    if ((threadIdx.x & 31) == 0) ws[threadIdx.x >> 5] = s;
    __syncthreads();
    if (threadIdx.x == 0) {
        float t = 0.f;
#pragma unroll
        for (int i = 0; i < 8; i++) t += ws[i];
        d_srow[b] = t;
    }
}

// ---------------- K2: lower median via 32-pass radix select ----------------
__global__ void k_median() {
    extern __shared__ u32 keys[];   // 16384 keys = 64 KB (dynamic)
    __shared__ int cnt;
    int tid = threadIdx.x;
    for (int i = tid; i < B_ROWS; i += 1024) {
        u32 u = __float_as_uint(d_srow[i]);
        keys[i] = (u & 0x80000000u) ? ~u : (u | 0x80000000u);  // order-preserving
    }
    __syncthreads();

    u32 prefix = 0;
    int k = (B_ROWS - 1) / 2;      // lower median rank (0-based)
    for (int bit = 31; bit >= 0; --bit) {
        u32 bmask = 1u << bit;
        u32 hmask = ~((bmask << 1) - 1u);
        if (tid == 0) cnt = 0;
        __syncthreads();
        int local = 0;
        for (int i = tid; i < B_ROWS; i += 1024) {
            u32 kv = keys[i];
            if ((((kv ^ prefix) & hmask) == 0) && !(kv & bmask)) local++;
        }
        atomicAdd(&cnt, local);
        __syncthreads();
        int c0 = cnt;
        if (k >= c0) { prefix |= bmask; k -= c0; }
        __syncthreads();
    }
    if (tid == 0) {
        u32 u = (prefix & 0x80000000u) ? (prefix & 0x7FFFFFFFu) : ~prefix;
        d_med = __uint_as_float(u);
    }
}

// ---------------- K3: fused norm + GEMM1 (3xTF32, K-split, pipelined) ------
// grid (256, 4): x-dim = 64-row tile, y-dim = 1024-K slab. 256 thr = 8 warps.
// Register double-buffer: prefetch next chunk's x/W during mma phase.
#define G1_ALD 36
#define G1_WLD 72
__global__ __launch_bounds__(256) void k_gemm1(const float* __restrict__ x,
                                               const float* __restrict__ Win) {
    __shared__ float rfac[64];
    __shared__ u32 Ahi[64 * G1_ALD], Alo[64 * G1_ALD];   // [row][k]
    __shared__ u32 Whi[32 * G1_WLD], Wlo[32 * G1_WLD];   // [k][col]
    __shared__ double red[512];
    int tid = threadIdx.x;
    int r0  = blockIdx.x * 64;
    int kb  = blockIdx.y * KSLAB;
    if (tid < 64) rfac[tid] = d_med / d_srow[r0 + tid];
    __syncthreads();

    int warp = tid >> 5, lane = tid & 31;
    int wm = warp >> 1, wn = warp & 1;
    int g = lane >> 2, t = lane & 3;
    int lrow = tid >> 2, lk = (tid & 3) * 8;     // A loader: 4 thr/row, 8 k each
    int wrow = tid >> 3, wcol = (tid & 7) * 8;   // W loader: 8 thr/row, 8 cols each
    float rf = rfac[lrow];

    const float* xp = x + (size_t)(r0 + lrow) * D_COLS + kb + lk;
    const float* wp = Win + (size_t)(kb + wrow) * 64 + wcol;

    float cfr[4][4];
#pragma unroll
    for (int nt = 0; nt < 4; nt++)
#pragma unroll
        for (int i = 0; i < 4; i++) cfr[nt][i] = 0.f;
    double dsum = 0.0, dsq = 0.0;

    // prefetch chunk 0
    float4 xv0 = *(const float4*)(xp);
    float4 xv1 = *(const float4*)(xp + 4);
    float4 wv0 = *(const float4*)(wp);
    float4 wv1 = *(const float4*)(wp + 4);

    const int NCH = KSLAB / 32;   // 32 chunks
    for (int c = 0; c < NCH; c++) {
        // ---- compute from regs: norm + tf32 split + stats ----
        float n[8] = {
            __logf(fmaf(xv0.x, rf, 1.f)), __logf(fmaf(xv0.y, rf, 1.f)),
            __logf(fmaf(xv0.z, rf, 1.f)), __logf(fmaf(xv0.w, rf, 1.f)),
            __logf(fmaf(xv1.x, rf, 1.f)), __logf(fmaf(xv1.y, rf, 1.f)),
            __logf(fmaf(xv1.z, rf, 1.f)), __logf(fmaf(xv1.w, rf, 1.f)) };
        float wv[8] = {wv0.x, wv0.y, wv0.z, wv0.w, wv1.x, wv1.y, wv1.z, wv1.w};
        u32 nh[8], nl[8], wh[8], wl[8];
        float ls = 0.f, lq = 0.f;
#pragma unroll
        for (int j = 0; j < 8; j++) {
            ls += n[j]; lq = fmaf(n[j], n[j], lq);
            nh[j] = to_tf32(n[j]);
            nl[j] = to_tf32(n[j] - __uint_as_float(nh[j]));
            wh[j] = to_tf32(wv[j]);
            wl[j] = to_tf32(wv[j] - __uint_as_float(wh[j]));
        }
        dsum += (double)ls; dsq += (double)lq;

        __syncthreads();   // previous mma done reading smem
        {
            u32* ah = Ahi + lrow * G1_ALD + lk;
            u32* al = Alo + lrow * G1_ALD + lk;
            *(uint4*)(ah)     = make_uint4(nh[0], nh[1], nh[2], nh[3]);
            *(uint4*)(ah + 4) = make_uint4(nh[4], nh[5], nh[6], nh[7]);
            *(uint4*)(al)     = make_uint4(nl[0], nl[1], nl[2], nl[3]);
            *(uint4*)(al + 4) = make_uint4(nl[4], nl[5], nl[6], nl[7]);
            u32* whp = Whi + wrow * G1_WLD + wcol;
            u32* wlp = Wlo + wrow * G1_WLD + wcol;
            *(uint4*)(whp)     = make_uint4(wh[0], wh[1], wh[2], wh[3]);
            *(uint4*)(whp + 4) = make_uint4(wh[4], wh[5], wh[6], wh[7]);
            *(uint4*)(wlp)     = make_uint4(wl[0], wl[1], wl[2], wl[3]);
            *(uint4*)(wlp + 4) = make_uint4(wl[4], wl[5], wl[6], wl[7]);
        }
        // ---- issue next chunk's loads (hidden under mma phase) ----
        if (c + 1 < NCH) {
            const float* xn = xp + (c + 1) * 32;
            const float* wn = wp + (size_t)(c + 1) * 32 * 64;
            xv0 = *(const float4*)(xn);
            xv1 = *(const float4*)(xn + 4);
            wv0 = *(const float4*)(wn);
            wv1 = *(const float4*)(wn + 4);
        }
        __syncthreads();   // smem tiles visible

        // ---- mma: 4 k-steps of 8 ----
        int arow0 = wm * 16 + g;
#pragma unroll
        for (int kt = 0; kt < 4; kt++) {
            int k0 = kt * 8;
            u32 ah[4], al[4];
            ah[0] = Ahi[arow0 * G1_ALD + k0 + t];
            ah[1] = Ahi[(arow0 + 8) * G1_ALD + k0 + t];
            ah[2] = Ahi[arow0 * G1_ALD + k0 + t + 4];
            ah[3] = Ahi[(arow0 + 8) * G1_ALD + k0 + t + 4];
            al[0] = Alo[arow0 * G1_ALD + k0 + t];
            al[1] = Alo[(arow0 + 8) * G1_ALD + k0 + t];
            al[2] = Alo[arow0 * G1_ALD + k0 + t + 4];
            al[3] = Alo[(arow0 + 8) * G1_ALD + k0 + t + 4];
#pragma unroll
            for (int nt = 0; nt < 4; nt++) {
                int bc = wn * 32 + nt * 8 + g;
                u32 bh[2] = { Whi[(k0 + t) * G1_WLD + bc], Whi[(k0 + t + 4) * G1_WLD + bc] };
                u32 bl[2] = { Wlo[(k0 + t) * G1_WLD + bc], Wlo[(k0 + t + 4) * G1_WLD + bc] };
                mma1688(cfr[nt], ah, bh);
                mma1688(cfr[nt], al, bh);
                mma1688(cfr[nt], ah, bl);
            }
        }
    }
    // ---- writeback partial G for this slab ----
    size_t gbase = (size_t)blockIdx.y * B_ROWS * 64;
#pragma unroll
    for (int nt = 0; nt < 4; nt++) {
        int col = wn * 32 + nt * 8 + t * 2;
        int rA = r0 + wm * 16 + g, rB = rA + 8;
        *(float2*)&d_Gp[gbase + (size_t)rA * 64 + col] = make_float2(cfr[nt][0], cfr[nt][1]);
        *(float2*)&d_Gp[gbase + (size_t)rB * 64 + col] = make_float2(cfr[nt][2], cfr[nt][3]);
    }
    // ---- global norm stats reduction ----
    red[tid] = dsum; red[256 + tid] = dsq;
    __syncthreads();
    for (int s = 128; s > 0; s >>= 1) {
        if (tid < s) { red[tid] += red[tid + s]; red[256 + tid] += red[256 + tid + s]; }
        __syncthreads();
    }
    if (tid == 0) {
        atomicAdd(&d_nsum[0], red[0]);
        atomicAdd(&d_nsum[1], red[256]);
    }
}

// ---------------- K4: reduce G slabs + column stats ------------------------
__global__ __launch_bounds__(256) void k_colstatsG() {
    int col = threadIdx.x & 63, rg = threadIdx.x >> 6;
    int r0 = blockIdx.x * 256;
    double s = 0.0, q = 0.0;
    const size_t SL = (size_t)B_ROWS * 64;
    for (int r = rg; r < 256; r += 4) {
        size_t idx = (size_t)(r0 + r) * 64 + col;
        float v = (d_Gp[idx] + d_Gp[SL + idx]) + (d_Gp[2 * SL + idx] + d_Gp[3 * SL + idx]);
        d_G[idx] = v;
        s += (double)v; q += (double)v * (double)v;
    }
    __shared__ double sh[256], shq[256];
    sh[threadIdx.x] = s; shq[threadIdx.x] = q;
    __syncthreads();
    if (rg == 0) {
#pragma unroll
        for (int g = 1; g < 4; g++) { s += sh[col + 64 * g]; q += shq[col + 64 * g]; }
        atomicAdd(&d_s1[col], s);
        atomicAdd(&d_q1[col], q);
    }
}

// ---------------- K5: layer-1 BN+ReLU -> h1 @ W_enc + b_enc (+stats) -------
__global__ __launch_bounds__(256) void k_mlp2(const float* __restrict__ g1,
                                              const float* __restrict__ bt1,
                                              const float* __restrict__ Wenc,
                                              const float* __restrict__ benc) {
    __shared__ float mu1[64], sc1[64], bts[64];
    __shared__ float We[64 * 32];
    __shared__ float be[32];
    __shared__ float h1buf[8][64];
    int tid = threadIdx.x;
    if (tid < 64) {
        double tot = d_nsum[0], totq = d_nsum[1];
        double sigma2 = (totq - tot * tot / BD_TOT) / (BD_TOT - 1.0);
        double mu  = d_s1[tid] / 16384.0;
        double var = d_q1[tid] / 16384.0 - mu * mu;
        mu1[tid] = (float)mu;
        sc1[tid] = g1[tid] * (float)rsqrt(var + 1e-5 * sigma2);
        bts[tid] = bt1[tid];
    }
    for (int i = tid; i < 64 * 32; i += 256) We[i] = Wenc[i];
    if (tid < 32) be[tid] = benc[tid];
    __syncthreads();

    int w = tid >> 5, lane = tid & 31;
    int rbase = blockIdx.x * 64 + w * 8;
    float ls = 0.f, lq = 0.f;
    for (int rr = 0; rr < 8; rr++) {
        int row = rbase + rr;
        float a0 = d_G[(size_t)row * 64 + lane];
        float a1 = d_G[(size_t)row * 64 + 32 + lane];
        h1buf[w][lane]      = fmaxf(fmaf(a0 - mu1[lane],      sc1[lane],      bts[lane]),      0.f);
        h1buf[w][32 + lane] = fmaxf(fmaf(a1 - mu1[32 + lane], sc1[32 + lane], bts[32 + lane]), 0.f);
        __syncwarp();
        float acc = be[lane];
#pragma unroll
        for (int k = 0; k < 64; k++) acc = fmaf(h1buf[w][k], We[k * 32 + lane], acc);
        d_H2[(size_t)row * 32 + lane] = acc;
        ls += acc; lq += acc * acc;
        __syncwarp();
    }
    atomicAdd(&d_s2[lane], (double)ls);
    atomicAdd(&d_q2[lane], (double)lq);
}

// ---------------- K6: layer-2 BN+ReLU -> h2 @ W_dec + b_dec (+stats) -------
__global__ __launch_bounds__(256) void k_mlp3(const float* __restrict__ g2,
                                              const float* __restrict__ bt2,
                                              const float* __restrict__ Wdec,
                                              const float* __restrict__ bdec) {
    __shared__ float mu2[32], sc2[32], bts[32];
    __shared__ float Wd[32 * 64];
    __shared__ float bd[64];
    __shared__ float h2buf[8][32];
    int tid = threadIdx.x;
    if (tid < 32) {
        double mu  = d_s2[tid] / 16384.0;
        double var = d_q2[tid] / 16384.0 - mu * mu;
        mu2[tid] = (float)mu;
        sc2[tid] = g2[tid] * (float)rsqrt(var + 1e-5);
        bts[tid] = bt2[tid];
    }
    for (int i = tid; i < 32 * 64; i += 256) Wd[i] = Wdec[i];
    if (tid < 64) bd[tid] = bdec[tid];
    __syncthreads();

    int w = tid >> 5, lane = tid & 31;
    int rbase = blockIdx.x * 64 + w * 8;
    float ls0 = 0.f, lq0 = 0.f, ls1 = 0.f, lq1 = 0.f;
    for (int rr = 0; rr < 8; rr++) {
        int row = rbase + rr;
        float v = d_H2[(size_t)row * 32 + lane];
        h2buf[w][lane] = fmaxf(fmaf(v - mu2[lane], sc2[lane], bts[lane]), 0.f);
        __syncwarp();
        float acc0 = bd[lane], acc1 = bd[32 + lane];
#pragma unroll
        for (int k = 0; k < 32; k++) {
            float h = h2buf[w][k];
            acc0 = fmaf(h, Wd[k * 64 + lane],      acc0);
            acc1 = fmaf(h, Wd[k * 64 + 32 + lane], acc1);
        }
        d_H3[(size_t)row * 64 + lane]      = acc0;
        d_H3[(size_t)row * 64 + 32 + lane] = acc1;
        ls0 += acc0; lq0 += acc0 * acc0;
        ls1 += acc1; lq1 += acc1 * acc1;
        __syncwarp();
    }
    atomicAdd(&d_s3[lane],      (double)ls0);
    atomicAdd(&d_q3[lane],      (double)lq0);
    atomicAdd(&d_s3[32 + lane], (double)ls1);
    atomicAdd(&d_q3[32 + lane], (double)lq1);
}

// ---------------- K7: BN3+ReLU -> h3 @ {W_pi,W_m,W_th} + act (tf32 MMA) ----
#define AH_LD 68
#define WS_LD 136
__global__ __launch_bounds__(256, 2) void k_out(const float* __restrict__ g3,
                                                const float* __restrict__ bt3,
                                                const float* __restrict__ Wpi,
                                                const float* __restrict__ bpi,
                                                const float* __restrict__ Wm,
                                                const float* __restrict__ bm,
                                                const float* __restrict__ Wth,
                                                const float* __restrict__ bth,
                                                float* __restrict__ out) {
    extern __shared__ u32 smu[];
    u32*   Ah  = smu;                       // 128 x 68
    u32*   Wsm = smu + 128 * AH_LD;         // 64 x 136 (column-permuted)
    float* mu3 = (float*)(smu + 128 * AH_LD + 64 * WS_LD);
    float* sc3 = mu3 + 64;
    float* bts = sc3 + 64;
    float* bs  = bts + 64;                  // 128

    int tid = threadIdx.x;
    int mz  = blockIdx.z;
    const float* W  = (mz == 0) ? Wpi : ((mz == 1) ? Wm : Wth);
    const float* bb = (mz == 0) ? bpi : ((mz == 1) ? bm : bth);
    int c0 = blockIdx.x * 128, r0 = blockIdx.y * 128;

    if (tid < 64) {
        double mu  = d_s3[tid] / 16384.0;
        double var = d_q3[tid] / 16384.0 - mu * mu;
        mu3[tid] = (float)mu;
        sc3[tid] = g3[tid] * (float)rsqrt(var + 1e-5);
        bts[tid] = bt3[tid];
    }
    if (tid < 128) bs[tid] = bb[c0 + tid];
    __syncthreads();

    {
        int lr = tid >> 1, cb = (tid & 1) * 32;
        const float4* src = (const float4*)&d_H3[(size_t)(r0 + lr) * 64 + cb];
        u32* dst = Ah + lr * AH_LD + cb;
#pragma unroll
        for (int j = 0; j < 8; j++) {
            float4 v = src[j];
            int c = cb + j * 4;
            uint4 o;
            o.x = to_tf32(fmaxf(fmaf(v.x - mu3[c + 0], sc3[c + 0], bts[c + 0]), 0.f));
            o.y = to_tf32(fmaxf(fmaf(v.y - mu3[c + 1], sc3[c + 1], bts[c + 1]), 0.f));
            o.z = to_tf32(fmaxf(fmaf(v.z - mu3[c + 2], sc3[c + 2], bts[c + 2]), 0.f));
            o.w = to_tf32(fmaxf(fmaf(v.w - mu3[c + 3], sc3[c + 3], bts[c + 3]), 0.f));
            *(uint4*)(dst + j * 4) = o;
        }
        int kr = tid >> 2, wb = (tid & 3) * 32;
        const float* wsrc = &W[(size_t)kr * 4096 + c0 + wb];
        u32* wrow = Wsm + kr * WS_LD;
#pragma unroll
        for (int j = 0; j < 8; j++) {
            float4 v = *(const float4*)(wsrc + j * 4);
            int gc = wb + j * 4;
            int grp = gc >> 4, q = (gc & 15) >> 2;
            u32* base = wrow + grp * 16;
            uint2 loxy = make_uint2(to_tf32(v.x), to_tf32(v.y));
            uint2 lozw = make_uint2(to_tf32(v.z), to_tf32(v.w));
            *(uint2*)(base + 2 * q)     = loxy;
            *(uint2*)(base + 8 + 2 * q) = lozw;
        }
    }
    __syncthreads();

    int warp = tid >> 5, lane = tid & 31;
    int wm = warp >> 1, wn = warp & 1;
    int g = lane >> 2, t = lane & 3;
    int arow0 = wm * 32 + g;
    int bcol0 = wn * 64 + g;

    float cfr[2][8][4];
#pragma unroll
    for (int mt = 0; mt < 2; mt++)
#pragma unroll
        for (int nt = 0; nt < 8; nt++)
#pragma unroll
            for (int i = 0; i < 4; i++) cfr[mt][nt][i] = 0.f;

#pragma unroll
    for (int kt = 0; kt < 8; kt++) {
        int k0 = kt * 8;
        u32 bfr[8][2];
#pragma unroll
        for (int nt = 0; nt < 8; nt++) {
            bfr[nt][0] = Wsm[(k0 + t) * WS_LD + bcol0 + nt * 8];
            bfr[nt][1] = Wsm[(k0 + t + 4) * WS_LD + bcol0 + nt * 8];
        }
        u32 afr[2][4];
#pragma unroll
        for (int mt = 0; mt < 2; mt++) {
            int r = arow0 + mt * 16;
            afr[mt][0] = Ah[r * AH_LD + k0 + t];
            afr[mt][1] = Ah[(r + 8) * AH_LD + k0 + t];
            afr[mt][2] = Ah[r * AH_LD + k0 + t + 4];
            afr[mt][3] = Ah[(r + 8) * AH_LD + k0 + t + 4];
        }
#pragma unroll
        for (int mt = 0; mt < 2; mt++)
#pragma unroll
            for (int nt = 0; nt < 8; nt++)
                mma1688(cfr[mt][nt], afr[mt], bfr[nt]);
    }

    size_t obase = (size_t)mz * (size_t)B_ROWS * D_COLS + (size_t)r0 * D_COLS + c0;
#pragma unroll
    for (int mt = 0; mt < 2; mt++) {
        int rA = wm * 32 + mt * 16 + g;
        int rB = rA + 8;
#pragma unroll
        for (int p = 0; p < 4; p++) {
            int gcb = wn * 64 + p * 16 + t * 4;
            float4 bv = *(float4*)&bs[gcb];
            float4 zA = make_float4(cfr[mt][2 * p][0] + bv.x, cfr[mt][2 * p][1] + bv.y,
                                    cfr[mt][2 * p + 1][0] + bv.z, cfr[mt][2 * p + 1][1] + bv.w);
            float4 zB = make_float4(cfr[mt][2 * p][2] + bv.x, cfr[mt][2 * p][3] + bv.y,
                                    cfr[mt][2 * p + 1][2] + bv.z, cfr[mt][2 * p + 1][3] + bv.w);
            if (mz == 0) {
                zA.x = fast_sigmoid(zA.x); zA.y = fast_sigmoid(zA.y);
                zA.z = fast_sigmoid(zA.z); zA.w = fast_sigmoid(zA.w);
                zB.x = fast_sigmoid(zB.x); zB.y = fast_sigmoid(zB.y);
                zB.z = fast_sigmoid(zB.z); zB.w = fast_sigmoid(zB.w);
            } else {
                zA.x = __expf(zA.x); zA.y = __expf(zA.y);
                zA.z = __expf(zA.z); zA.w = __expf(zA.w);
                zB.x = __expf(zB.x); zB.y = __expf(zB.y);
                zB.z = __expf(zB.z); zB.w = __expf(zB.w);
            }
            *(float4*)&out[obase + (size_t)rA * D_COLS + gcb] = zA;
            *(float4*)&out[obase + (size_t)rB * D_COLS + gcb] = zB;
        }
    }
}

// ---------------- launch ----------------------------------------------------
extern "C" void kernel_launch(void* const* d_in, const int* in_sizes, int n_in,
                              void* d_out, int out_size) {
    const float* x    = (const float*)d_in[0];
    const float* Win  = (const float*)d_in[1];
    const float* g1   = (const float*)d_in[3];
    const float* bt1  = (const float*)d_in[4];
    const float* Wenc = (const float*)d_in[5];
    const float* benc = (const float*)d_in[6];
    const float* g2   = (const float*)d_in[7];
    const float* bt2  = (const float*)d_in[8];
    const float* Wdec = (const float*)d_in[9];
    const float* bdec = (const float*)d_in[10];
    const float* g3   = (const float*)d_in[11];
    const float* bt3  = (const float*)d_in[12];
    const float* Wpi  = (const float*)d_in[13];
    const float* bpi  = (const float*)d_in[14];
    const float* Wm   = (const float*)d_in[15];
    const float* bm   = (const float*)d_in[16];
    const float* Wth  = (const float*)d_in[17];
    const float* bth  = (const float*)d_in[18];
    float* out = (float*)d_out;

    const int koutSmem = (128 * AH_LD + 64 * WS_LD) * 4 + (64 * 3 + 128) * 4;

    cudaFuncSetAttribute(k_median, cudaFuncAttributeMaxDynamicSharedMemorySize, 65536);
    cudaFuncSetAttribute(k_out,    cudaFuncAttributeMaxDynamicSharedMemorySize, koutSmem);

    k_zero<<<1, 64>>>();
    k_rowsum<<<B_ROWS, 256>>>(x);
    k_median<<<1, 1024, 65536>>>();
    dim3 g1grid(B_ROWS / 64, NSLAB);
    k_gemm1<<<g1grid, 256>>>(x, Win);
    k_colstatsG<<<64, 256>>>();
    k_mlp2<<<B_ROWS / 64, 256>>>(g1, bt1, Wenc, benc);
    k_mlp3<<<B_ROWS / 64, 256>>>(g2, bt2, Wdec, bdec);
    dim3 g(D_COLS / 128, B_ROWS / 128, 3);
    k_out<<<g, 256, koutSmem>>>(g3, bt3, Wpi, bpi, Wm, bm, Wth, bth, out);
}

// round 9
// speedup vs baseline: 1.4487x; 1.1789x over previous
#include <cuda_runtime.h>
#include <math.h>

#define B_ROWS 16384
#define D_COLS 4096
#define H1N 64
#define H2N 32
#define BD_TOT (16384.0*4096.0)
#define NSLAB 4
#define KSLAB 1024

typedef unsigned long long u64;
typedef unsigned int u32;

// ---------------- scratch (device globals, no allocations) ----------------
__device__ float  d_srow[B_ROWS];
__device__ float  d_med;
__device__ double d_nsum[2];                 // sum(norm), sum(norm^2)
__device__ float  d_Gp[NSLAB * B_ROWS * H1N]; // partial G per K-slab
__device__ float  d_G[B_ROWS * H1N];         // norm_raw @ W_in
__device__ double d_s1[H1N], d_q1[H1N];      // col stats of G
__device__ float  d_H2[B_ROWS * H2N];        // h1 @ W_enc + b_enc
__device__ double d_s2[H2N], d_q2[H2N];
__device__ float  d_H3[B_ROWS * H1N];        // h2 @ W_dec + b_dec
__device__ double d_s3[H1N], d_q3[H1N];

// ---------------- mma helpers -----------------------------------------------
__device__ __forceinline__ u32 to_tf32(float f) {
    u32 u; asm("cvt.rna.tf32.f32 %0, %1;" : "=r"(u) : "f"(f)); return u;
}
__device__ __forceinline__ void mma1688(float c[4], const u32 a[4], const u32 b[2]) {
    asm volatile(
        "mma.sync.aligned.m16n8k8.row.col.f32.tf32.tf32.f32 "
        "{%0,%1,%2,%3},{%4,%5,%6,%7},{%8,%9},{%0,%1,%2,%3};"
        : "+f"(c[0]), "+f"(c[1]), "+f"(c[2]), "+f"(c[3])
        : "r"(a[0]), "r"(a[1]), "r"(a[2]), "r"(a[3]), "r"(b[0]), "r"(b[1]));
}
// bf16 m16n8k16: a = 4 regs (8 bf16), b = 2 regs (4 bf16)
__device__ __forceinline__ void mma16816bf(float c[4], const u32 a[4], const u32 b[2]) {
    asm volatile(
        "mma.sync.aligned.m16n8k16.row.col.f32.bf16.bf16.f32 "
        "{%0,%1,%2,%3},{%4,%5,%6,%7},{%8,%9},{%0,%1,%2,%3};"
        : "+f"(c[0]), "+f"(c[1]), "+f"(c[2]), "+f"(c[3])
        : "r"(a[0]), "r"(a[1]), "r"(a[2]), "r"(a[3]), "r"(b[0]), "r"(b[1]));
}
// pack two floats to bf16x2: lo -> bits[0:16), hi -> bits[16:32)
__device__ __forceinline__ u32 pack_bf16(float lo, float hi) {
    u32 r; asm("cvt.rn.bf16x2.f32 %0, %1, %2;" : "=r"(r) : "f"(hi), "f"(lo)); return r;
}
__device__ __forceinline__ float fast_sigmoid(float z) {
    return __fdividef(1.f, 1.f + __expf(-z));
}

// ---------------- K0: zero the accumulators --------------------------------
__global__ void k_zero() {
    int t = threadIdx.x;
    if (t < 2)   d_nsum[t] = 0.0;
    if (t < H1N) { d_s1[t] = 0.0; d_q1[t] = 0.0; d_s3[t] = 0.0; d_q3[t] = 0.0; }
    if (t < H2N) { d_s2[t] = 0.0; d_q2[t] = 0.0; }
}

// ---------------- K1: per-row sums of x ------------------------------------
__global__ __launch_bounds__(256) void k_rowsum(const float* __restrict__ x) {
    int b = blockIdx.x;
    const float4* row = (const float4*)(x + (size_t)b * D_COLS);
    float s = 0.f;
#pragma unroll
    for (int i = 0; i < 4; i++) {
        float4 v = row[threadIdx.x + i * 256];
        s += (v.x + v.y) + (v.z + v.w);
    }
#pragma unroll
    for (int o = 16; o > 0; o >>= 1) s += __shfl_down_sync(0xffffffffu, s, o);
    __shared__ float ws[8];
    if ((threadIdx.x & 31) == 0) ws[threadIdx.x >> 5] = s;
    __syncthreads();
    if (threadIdx.x == 0) {
        float t = 0.f;
#pragma unroll
        for (int i = 0; i < 8; i++) t += ws[i];
        d_srow[b] = t;
    }
}

// ---------------- K2: lower median via 32-pass radix select ----------------
__global__ void k_median() {
    extern __shared__ u32 keys[];
    __shared__ int cnt;
    int tid = threadIdx.x;
    for (int i = tid; i < B_ROWS; i += 1024) {
        u32 u = __float_as_uint(d_srow[i]);
        keys[i] = (u & 0x80000000u) ? ~u : (u | 0x80000000u);
    }
    __syncthreads();

    u32 prefix = 0;
    int k = (B_ROWS - 1) / 2;
    for (int bit = 31; bit >= 0; --bit) {
        u32 bmask = 1u << bit;
        u32 hmask = ~((bmask << 1) - 1u);
        if (tid == 0) cnt = 0;
        __syncthreads();
        int local = 0;
        for (int i = tid; i < B_ROWS; i += 1024) {
            u32 kv = keys[i];
            if ((((kv ^ prefix) & hmask) == 0) && !(kv & bmask)) local++;
        }
        atomicAdd(&cnt, local);
        __syncthreads();
        int c0 = cnt;
        if (k >= c0) { prefix |= bmask; k -= c0; }
        __syncthreads();
    }
    if (tid == 0) {
        u32 u = (prefix & 0x80000000u) ? (prefix & 0x7FFFFFFFu) : ~prefix;
        d_med = __uint_as_float(u);
    }
}

// ---------------- K3: fused norm + GEMM1 (3xTF32, K-split, pipelined) ------
#define G1_ALD 36
#define G1_WLD 72
__global__ __launch_bounds__(256) void k_gemm1(const float* __restrict__ x,
                                               const float* __restrict__ Win) {
    __shared__ float rfac[64];
    __shared__ u32 Ahi[64 * G1_ALD], Alo[64 * G1_ALD];
    __shared__ u32 Whi[32 * G1_WLD], Wlo[32 * G1_WLD];
    __shared__ double red[512];
    int tid = threadIdx.x;
    int r0  = blockIdx.x * 64;
    int kb  = blockIdx.y * KSLAB;
    if (tid < 64) rfac[tid] = d_med / d_srow[r0 + tid];
    __syncthreads();

    int warp = tid >> 5, lane = tid & 31;
    int wm = warp >> 1, wn = warp & 1;
    int g = lane >> 2, t = lane & 3;
    int lrow = tid >> 2, lk = (tid & 3) * 8;
    int wrow = tid >> 3, wcol = (tid & 7) * 8;
    float rf = rfac[lrow];

    const float* xp = x + (size_t)(r0 + lrow) * D_COLS + kb + lk;
    const float* wp = Win + (size_t)(kb + wrow) * 64 + wcol;

    float cfr[4][4];
#pragma unroll
    for (int nt = 0; nt < 4; nt++)
#pragma unroll
        for (int i = 0; i < 4; i++) cfr[nt][i] = 0.f;
    double dsum = 0.0, dsq = 0.0;

    float4 xv0 = *(const float4*)(xp);
    float4 xv1 = *(const float4*)(xp + 4);
    float4 wv0 = *(const float4*)(wp);
    float4 wv1 = *(const float4*)(wp + 4);

    const int NCH = KSLAB / 32;
    for (int c = 0; c < NCH; c++) {
        float n[8] = {
            __logf(fmaf(xv0.x, rf, 1.f)), __logf(fmaf(xv0.y, rf, 1.f)),
            __logf(fmaf(xv0.z, rf, 1.f)), __logf(fmaf(xv0.w, rf, 1.f)),
            __logf(fmaf(xv1.x, rf, 1.f)), __logf(fmaf(xv1.y, rf, 1.f)),
            __logf(fmaf(xv1.z, rf, 1.f)), __logf(fmaf(xv1.w, rf, 1.f)) };
        float wv[8] = {wv0.x, wv0.y, wv0.z, wv0.w, wv1.x, wv1.y, wv1.z, wv1.w};
        u32 nh[8], nl[8], wh[8], wl[8];
        float ls = 0.f, lq = 0.f;
#pragma unroll
        for (int j = 0; j < 8; j++) {
            ls += n[j]; lq = fmaf(n[j], n[j], lq);
            nh[j] = to_tf32(n[j]);
            nl[j] = to_tf32(n[j] - __uint_as_float(nh[j]));
            wh[j] = to_tf32(wv[j]);
            wl[j] = to_tf32(wv[j] - __uint_as_float(wh[j]));
        }
        dsum += (double)ls; dsq += (double)lq;

        __syncthreads();
        {
            u32* ah = Ahi + lrow * G1_ALD + lk;
            u32* al = Alo + lrow * G1_ALD + lk;
            *(uint4*)(ah)     = make_uint4(nh[0], nh[1], nh[2], nh[3]);
            *(uint4*)(ah + 4) = make_uint4(nh[4], nh[5], nh[6], nh[7]);
            *(uint4*)(al)     = make_uint4(nl[0], nl[1], nl[2], nl[3]);
            *(uint4*)(al + 4) = make_uint4(nl[4], nl[5], nl[6], nl[7]);
            u32* whp = Whi + wrow * G1_WLD + wcol;
            u32* wlp = Wlo + wrow * G1_WLD + wcol;
            *(uint4*)(whp)     = make_uint4(wh[0], wh[1], wh[2], wh[3]);
            *(uint4*)(whp + 4) = make_uint4(wh[4], wh[5], wh[6], wh[7]);
            *(uint4*)(wlp)     = make_uint4(wl[0], wl[1], wl[2], wl[3]);
            *(uint4*)(wlp + 4) = make_uint4(wl[4], wl[5], wl[6], wl[7]);
        }
        if (c + 1 < NCH) {
            const float* xn = xp + (c + 1) * 32;
            const float* wn = wp + (size_t)(c + 1) * 32 * 64;
            xv0 = *(const float4*)(xn);
            xv1 = *(const float4*)(xn + 4);
            wv0 = *(const float4*)(wn);
            wv1 = *(const float4*)(wn + 4);
        }
        __syncthreads();

        int arow0 = wm * 16 + g;
#pragma unroll
        for (int kt = 0; kt < 4; kt++) {
            int k0 = kt * 8;
            u32 ah[4], al[4];
            ah[0] = Ahi[arow0 * G1_ALD + k0 + t];
            ah[1] = Ahi[(arow0 + 8) * G1_ALD + k0 + t];
            ah[2] = Ahi[arow0 * G1_ALD + k0 + t + 4];
            ah[3] = Ahi[(arow0 + 8) * G1_ALD + k0 + t + 4];
            al[0] = Alo[arow0 * G1_ALD + k0 + t];
            al[1] = Alo[(arow0 + 8) * G1_ALD + k0 + t];
            al[2] = Alo[arow0 * G1_ALD + k0 + t + 4];
            al[3] = Alo[(arow0 + 8) * G1_ALD + k0 + t + 4];
#pragma unroll
            for (int nt = 0; nt < 4; nt++) {
                int bc = wn * 32 + nt * 8 + g;
                u32 bh[2] = { Whi[(k0 + t) * G1_WLD + bc], Whi[(k0 + t + 4) * G1_WLD + bc] };
                u32 bl[2] = { Wlo[(k0 + t) * G1_WLD + bc], Wlo[(k0 + t + 4) * G1_WLD + bc] };
                mma1688(cfr[nt], ah, bh);
                mma1688(cfr[nt], al, bh);
                mma1688(cfr[nt], ah, bl);
            }
        }
    }
    size_t gbase = (size_t)blockIdx.y * B_ROWS * 64;
#pragma unroll
    for (int nt = 0; nt < 4; nt++) {
        int col = wn * 32 + nt * 8 + t * 2;
        int rA = r0 + wm * 16 + g, rB = rA + 8;
        *(float2*)&d_Gp[gbase + (size_t)rA * 64 + col] = make_float2(cfr[nt][0], cfr[nt][1]);
        *(float2*)&d_Gp[gbase + (size_t)rB * 64 + col] = make_float2(cfr[nt][2], cfr[nt][3]);
    }
    red[tid] = dsum; red[256 + tid] = dsq;
    __syncthreads();
    for (int s = 128; s > 0; s >>= 1) {
        if (tid < s) { red[tid] += red[tid + s]; red[256 + tid] += red[256 + tid + s]; }
        __syncthreads();
    }
    if (tid == 0) {
        atomicAdd(&d_nsum[0], red[0]);
        atomicAdd(&d_nsum[1], red[256]);
    }
}

// ---------------- K4: reduce G slabs + column stats ------------------------
__global__ __launch_bounds__(256) void k_colstatsG() {
    int col = threadIdx.x & 63, rg = threadIdx.x >> 6;
    int r0 = blockIdx.x * 256;
    double s = 0.0, q = 0.0;
    const size_t SL = (size_t)B_ROWS * 64;
    for (int r = rg; r < 256; r += 4) {
        size_t idx = (size_t)(r0 + r) * 64 + col;
        float v = (d_Gp[idx] + d_Gp[SL + idx]) + (d_Gp[2 * SL + idx] + d_Gp[3 * SL + idx]);
        d_G[idx] = v;
        s += (double)v; q += (double)v * (double)v;
    }
    __shared__ double sh[256], shq[256];
    sh[threadIdx.x] = s; shq[threadIdx.x] = q;
    __syncthreads();
    if (rg == 0) {
#pragma unroll
        for (int g = 1; g < 4; g++) { s += sh[col + 64 * g]; q += shq[col + 64 * g]; }
        atomicAdd(&d_s1[col], s);
        atomicAdd(&d_q1[col], q);
    }
}

// ---------------- K5: layer-1 BN+ReLU -> h1 @ W_enc + b_enc (+stats) -------
__global__ __launch_bounds__(256) void k_mlp2(const float* __restrict__ g1,
                                              const float* __restrict__ bt1,
                                              const float* __restrict__ Wenc,
                                              const float* __restrict__ benc) {
    __shared__ float mu1[64], sc1[64], bts[64];
    __shared__ float We[64 * 32];
    __shared__ float be[32];
    __shared__ float h1buf[8][64];
    int tid = threadIdx.x;
    if (tid < 64) {
        double tot = d_nsum[0], totq = d_nsum[1];
        double sigma2 = (totq - tot * tot / BD_TOT) / (BD_TOT - 1.0);
        double mu  = d_s1[tid] / 16384.0;
        double var = d_q1[tid] / 16384.0 - mu * mu;
        mu1[tid] = (float)mu;
        sc1[tid] = g1[tid] * (float)rsqrt(var + 1e-5 * sigma2);
        bts[tid] = bt1[tid];
    }
    for (int i = tid; i < 64 * 32; i += 256) We[i] = Wenc[i];
    if (tid < 32) be[tid] = benc[tid];
    __syncthreads();

    int w = tid >> 5, lane = tid & 31;
    int rbase = blockIdx.x * 64 + w * 8;
    float ls = 0.f, lq = 0.f;
    for (int rr = 0; rr < 8; rr++) {
        int row = rbase + rr;
        float a0 = d_G[(size_t)row * 64 + lane];
        float a1 = d_G[(size_t)row * 64 + 32 + lane];
        h1buf[w][lane]      = fmaxf(fmaf(a0 - mu1[lane],      sc1[lane],      bts[lane]),      0.f);
        h1buf[w][32 + lane] = fmaxf(fmaf(a1 - mu1[32 + lane], sc1[32 + lane], bts[32 + lane]), 0.f);
        __syncwarp();
        float acc = be[lane];
#pragma unroll
        for (int k = 0; k < 64; k++) acc = fmaf(h1buf[w][k], We[k * 32 + lane], acc);
        d_H2[(size_t)row * 32 + lane] = acc;
        ls += acc; lq += acc * acc;
        __syncwarp();
    }
    atomicAdd(&d_s2[lane], (double)ls);
    atomicAdd(&d_q2[lane], (double)lq);
}

// ---------------- K6: layer-2 BN+ReLU -> h2 @ W_dec + b_dec (+stats) -------
__global__ __launch_bounds__(256) void k_mlp3(const float* __restrict__ g2,
                                              const float* __restrict__ bt2,
                                              const float* __restrict__ Wdec,
                                              const float* __restrict__ bdec) {
    __shared__ float mu2[32], sc2[32], bts[32];
    __shared__ float Wd[32 * 64];
    __shared__ float bd[64];
    __shared__ float h2buf[8][32];
    int tid = threadIdx.x;
    if (tid < 32) {
        double mu  = d_s2[tid] / 16384.0;
        double var = d_q2[tid] / 16384.0 - mu * mu;
        mu2[tid] = (float)mu;
        sc2[tid] = g2[tid] * (float)rsqrt(var + 1e-5);
        bts[tid] = bt2[tid];
    }
    for (int i = tid; i < 32 * 64; i += 256) Wd[i] = Wdec[i];
    if (tid < 64) bd[tid] = bdec[tid];
    __syncthreads();

    int w = tid >> 5, lane = tid & 31;
    int rbase = blockIdx.x * 64 + w * 8;
    float ls0 = 0.f, lq0 = 0.f, ls1 = 0.f, lq1 = 0.f;
    for (int rr = 0; rr < 8; rr++) {
        int row = rbase + rr;
        float v = d_H2[(size_t)row * 32 + lane];
        h2buf[w][lane] = fmaxf(fmaf(v - mu2[lane], sc2[lane], bts[lane]), 0.f);
        __syncwarp();
        float acc0 = bd[lane], acc1 = bd[32 + lane];
#pragma unroll
        for (int k = 0; k < 32; k++) {
            float h = h2buf[w][k];
            acc0 = fmaf(h, Wd[k * 64 + lane],      acc0);
            acc1 = fmaf(h, Wd[k * 64 + 32 + lane], acc1);
        }
        d_H3[(size_t)row * 64 + lane]      = acc0;
        d_H3[(size_t)row * 64 + 32 + lane] = acc1;
        ls0 += acc0; lq0 += acc0 * acc0;
        ls1 += acc1; lq1 += acc1 * acc1;
        __syncwarp();
    }
    atomicAdd(&d_s3[lane],      (double)ls0);
    atomicAdd(&d_q3[lane],      (double)lq0);
    atomicAdd(&d_s3[32 + lane], (double)ls1);
    atomicAdd(&d_q3[32 + lane], (double)lq1);
}

// ---------------- K7: BN3+ReLU -> h3 @ {W_pi,W_m,W_th} + act (bf16 MMA) ----
// BM=128 x BN=128 tile, K=64 resident as bf16x2. 8 warps: 4(M) x 2(N).
// A: [row][k/2] bf16x2, stride 36 u32.  W: TRANSPOSED [col][k/2] bf16x2,
// stride 36 u32, with the 16-col-group permutation so the epilogue's C
// fragments of tile pairs form 4 contiguous gmem columns (float4 stores).
#define AH32 36
#define WS32 36
__global__ __launch_bounds__(256, 2) void k_out(const float* __restrict__ g3,
                                                const float* __restrict__ bt3,
                                                const float* __restrict__ Wpi,
                                                const float* __restrict__ bpi,
                                                const float* __restrict__ Wm,
                                                const float* __restrict__ bm,
                                                const float* __restrict__ Wth,
                                                const float* __restrict__ bth,
                                                float* __restrict__ out) {
    extern __shared__ u32 smu[];
    u32*   Ah  = smu;                        // 128 rows x 36 (32 halves + pad)
    u32*   Wsm = smu + 128 * AH32;           // 128 cols x 36 (32 halves + pad)
    float* mu3 = (float*)(smu + 128 * AH32 + 128 * WS32);
    float* sc3 = mu3 + 64;
    float* bts = sc3 + 64;
    float* bs  = bts + 64;                   // 128 (natural gmem-col order)

    int tid = threadIdx.x;
    int mz  = blockIdx.z;
    const float* W  = (mz == 0) ? Wpi : ((mz == 1) ? Wm : Wth);
    const float* bb = (mz == 0) ? bpi : ((mz == 1) ? bm : bth);
    int c0 = blockIdx.x * 128, r0 = blockIdx.y * 128;

    if (tid < 64) {
        double mu  = d_s3[tid] / 16384.0;
        double var = d_q3[tid] / 16384.0 - mu * mu;
        mu3[tid] = (float)mu;
        sc3[tid] = g3[tid] * (float)rsqrt(var + 1e-5);
        bts[tid] = bt3[tid];
    }
    if (tid < 128) bs[tid] = bb[c0 + tid];
    __syncthreads();

    {   // ---- A tile: 128x64, BN+ReLU, pack bf16x2 ----
        int lr = tid >> 1, cb = (tid & 1) * 32, hb = (tid & 1) * 16;
        const float4* src = (const float4*)&d_H3[(size_t)(r0 + lr) * 64 + cb];
        u32* dst = Ah + lr * AH32 + hb;
#pragma unroll
        for (int j = 0; j < 8; j++) {
            float4 v = src[j];
            int c = cb + j * 4;
            float e0 = fmaxf(fmaf(v.x - mu3[c + 0], sc3[c + 0], bts[c + 0]), 0.f);
            float e1 = fmaxf(fmaf(v.y - mu3[c + 1], sc3[c + 1], bts[c + 1]), 0.f);
            float e2 = fmaxf(fmaf(v.z - mu3[c + 2], sc3[c + 2], bts[c + 2]), 0.f);
            float e3 = fmaxf(fmaf(v.w - mu3[c + 3], sc3[c + 3], bts[c + 3]), 0.f);
            *(uint2*)(dst + j * 2) = make_uint2(pack_bf16(e0, e1), pack_bf16(e2, e3));
        }
        // ---- W tile: 64k x 128col -> transposed bf16x2, permuted cols ----
        // task: 2 k-rows x 4 cols; 1024 tasks over 4 iterations.
#pragma unroll
        for (int it = 0; it < 4; it++) {
            int task = tid + it * 256;
            int krp  = task >> 5;            // 0..31 (k half-index)
            int colq = (task & 31) * 4;      // col group of 4
            const float* w0 = W + (size_t)(krp * 2) * 4096 + c0 + colq;
            float4 va = *(const float4*)(w0);
            float4 vb = *(const float4*)(w0 + 4096);
            int grp = colq >> 4, q = (colq & 15) >> 2;
            u32* base = Wsm + (grp * 16) * WS32 + krp;
            base[(2 * q)     * WS32] = pack_bf16(va.x, vb.x);
            base[(2 * q + 1) * WS32] = pack_bf16(va.y, vb.y);
            base[(8 + 2 * q)     * WS32] = pack_bf16(va.z, vb.z);
            base[(8 + 2 * q + 1) * WS32] = pack_bf16(va.w, vb.w);
        }
    }
    __syncthreads();

    int warp = tid >> 5, lane = tid & 31;
    int wm = warp >> 1, wn = warp & 1;
    int g = lane >> 2, t = lane & 3;
    int arow0 = wm * 32 + g;
    int bcol0 = wn * 64 + g;

    float cfr[2][8][4];
#pragma unroll
    for (int mt = 0; mt < 2; mt++)
#pragma unroll
        for (int nt = 0; nt < 8; nt++)
#pragma unroll
            for (int i = 0; i < 4; i++) cfr[mt][nt][i] = 0.f;

#pragma unroll
    for (int kt = 0; kt < 4; kt++) {         // K=64 in 4 steps of 16
        int k0h = kt * 8;                    // half-index base
        u32 bfr[8][2];
#pragma unroll
        for (int nt = 0; nt < 8; nt++) {
            int col = bcol0 + nt * 8;
            bfr[nt][0] = Wsm[col * WS32 + k0h + t];
            bfr[nt][1] = Wsm[col * WS32 + k0h + t + 4];
        }
        u32 afr[2][4];
#pragma unroll
        for (int mt = 0; mt < 2; mt++) {
            int r = arow0 + mt * 16;
            afr[mt][0] = Ah[r * AH32 + k0h + t];
            afr[mt][1] = Ah[(r + 8) * AH32 + k0h + t];
            afr[mt][2] = Ah[r * AH32 + k0h + t + 4];
            afr[mt][3] = Ah[(r + 8) * AH32 + k0h + t + 4];
        }
#pragma unroll
        for (int mt = 0; mt < 2; mt++)
#pragma unroll
            for (int nt = 0; nt < 8; nt++)
                mma16816bf(cfr[mt][nt], afr[mt], bfr[nt]);
    }

    size_t obase = (size_t)mz * (size_t)B_ROWS * D_COLS + (size_t)r0 * D_COLS + c0;
#pragma unroll
    for (int mt = 0; mt < 2; mt++) {
        int rA = wm * 32 + mt * 16 + g;
        int rB = rA + 8;
#pragma unroll
        for (int p = 0; p < 4; p++) {        // tile pair (2p, 2p+1) -> 4 contiguous cols
            int gcb = wn * 64 + p * 16 + t * 4;
            float4 bv = *(float4*)&bs[gcb];
            float4 zA = make_float4(cfr[mt][2 * p][0] + bv.x, cfr[mt][2 * p][1] + bv.y,
                                    cfr[mt][2 * p + 1][0] + bv.z, cfr[mt][2 * p + 1][1] + bv.w);
            float4 zB = make_float4(cfr[mt][2 * p][2] + bv.x, cfr[mt][2 * p][3] + bv.y,
                                    cfr[mt][2 * p + 1][2] + bv.z, cfr[mt][2 * p + 1][3] + bv.w);
            if (mz == 0) {
                zA.x = fast_sigmoid(zA.x); zA.y = fast_sigmoid(zA.y);
                zA.z = fast_sigmoid(zA.z); zA.w = fast_sigmoid(zA.w);
                zB.x = fast_sigmoid(zB.x); zB.y = fast_sigmoid(zB.y);
                zB.z = fast_sigmoid(zB.z); zB.w = fast_sigmoid(zB.w);
            } else {
                zA.x = __expf(zA.x); zA.y = __expf(zA.y);
                zA.z = __expf(zA.z); zA.w = __expf(zA.w);
                zB.x = __expf(zB.x); zB.y = __expf(zB.y);
                zB.z = __expf(zB.z); zB.w = __expf(zB.w);
            }
            *(float4*)&out[obase + (size_t)rA * D_COLS + gcb] = zA;
            *(float4*)&out[obase + (size_t)rB * D_COLS + gcb] = zB;
        }
    }
}

// ---------------- launch ----------------------------------------------------
extern "C" void kernel_launch(void* const* d_in, const int* in_sizes, int n_in,
                              void* d_out, int out_size) {
    const float* x    = (const float*)d_in[0];
    const float* Win  = (const float*)d_in[1];
    const float* g1   = (const float*)d_in[3];
    const float* bt1  = (const float*)d_in[4];
    const float* Wenc = (const float*)d_in[5];
    const float* benc = (const float*)d_in[6];
    const float* g2   = (const float*)d_in[7];
    const float* bt2  = (const float*)d_in[8];
    const float* Wdec = (const float*)d_in[9];
    const float* bdec = (const float*)d_in[10];
    const float* g3   = (const float*)d_in[11];
    const float* bt3  = (const float*)d_in[12];
    const float* Wpi  = (const float*)d_in[13];
    const float* bpi  = (const float*)d_in[14];
    const float* Wm   = (const float*)d_in[15];
    const float* bm   = (const float*)d_in[16];
    const float* Wth  = (const float*)d_in[17];
    const float* bth  = (const float*)d_in[18];
    float* out = (float*)d_out;

    const int koutSmem = (128 * AH32 + 128 * WS32) * 4 + (64 * 3 + 128) * 4;

    cudaFuncSetAttribute(k_median, cudaFuncAttributeMaxDynamicSharedMemorySize, 65536);
    cudaFuncSetAttribute(k_out,    cudaFuncAttributeMaxDynamicSharedMemorySize, koutSmem);

    k_zero<<<1, 64>>>();
    k_rowsum<<<B_ROWS, 256>>>(x);
    k_median<<<1, 1024, 65536>>>();
    dim3 g1grid(B_ROWS / 64, NSLAB);
    k_gemm1<<<g1grid, 256>>>(x, Win);
    k_colstatsG<<<64, 256>>>();
    k_mlp2<<<B_ROWS / 64, 256>>>(g1, bt1, Wenc, benc);
    k_mlp3<<<B_ROWS / 64, 256>>>(g2, bt2, Wdec, bdec);
    dim3 g(D_COLS / 128, B_ROWS / 128, 3);
    k_out<<<g, 256, koutSmem>>>(g3, bt3, Wpi, bpi, Wm, bm, Wth, bth, out);
}

// round 10
// speedup vs baseline: 1.5400x; 1.0630x over previous
#include <cuda_runtime.h>
#include <cuda_bf16.h>
#include <math.h>

#define B_ROWS 16384
#define D_COLS 4096
#define H1N 64
#define H2N 32
#define BD_TOT (16384.0*4096.0)
#define NSLAB 4
#define KSLAB 1024

typedef unsigned long long u64;
typedef unsigned int u32;
typedef unsigned short us16;

// ---------------- scratch (device globals, no allocations) ----------------
__device__ float  d_srow[B_ROWS];
__device__ float  d_med;
__device__ double d_nsum[2];                 // sum(norm), sum(norm^2)
__device__ float  d_Gp[NSLAB * B_ROWS * H1N]; // partial G per K-slab
__device__ float  d_G[B_ROWS * H1N];         // norm_raw @ W_in
__device__ double d_s1[H1N], d_q1[H1N];      // col stats of G
__device__ float  d_H2[B_ROWS * H2N];        // h1 @ W_enc + b_enc
__device__ double d_s2[H2N], d_q2[H2N];
__device__ float  d_H3[B_ROWS * H1N];        // h2 @ W_dec + b_dec
__device__ double d_s3[H1N], d_q3[H1N];

// ---------------- mma helpers -----------------------------------------------
// bf16 m16n8k16: a = 4 regs (8 bf16), b = 2 regs (4 bf16)
__device__ __forceinline__ void mma16816bf(float c[4], const u32 a[4], const u32 b[2]) {
    asm volatile(
        "mma.sync.aligned.m16n8k16.row.col.f32.bf16.bf16.f32 "
        "{%0,%1,%2,%3},{%4,%5,%6,%7},{%8,%9},{%0,%1,%2,%3};"
        : "+f"(c[0]), "+f"(c[1]), "+f"(c[2]), "+f"(c[3])
        : "r"(a[0]), "r"(a[1]), "r"(a[2]), "r"(a[3]), "r"(b[0]), "r"(b[1]));
}
// pack two floats to bf16x2: lo -> bits[0:16), hi -> bits[16:32)
__device__ __forceinline__ u32 pack_bf16(float lo, float hi) {
    u32 r; asm("cvt.rn.bf16x2.f32 %0, %1, %2;" : "=r"(r) : "f"(hi), "f"(lo)); return r;
}
__device__ __forceinline__ u32 pack_us(us16 lo, us16 hi) {
    return (u32)lo | ((u32)hi << 16);
}
// hi/lo bf16 split: v ~= hi + lo with |lo| <~ 2^-9 |v|
__device__ __forceinline__ void bf_split(float v, us16 &h, us16 &l) {
    __nv_bfloat16 hb = __float2bfloat16(v);
    float hf = __bfloat162float(hb);
    __nv_bfloat16 lb = __float2bfloat16(v - hf);
    h = __bfloat16_as_ushort(hb);
    l = __bfloat16_as_ushort(lb);
}
__device__ __forceinline__ float fast_sigmoid(float z) {
    return __fdividef(1.f, 1.f + __expf(-z));
}

// ---------------- K0: zero the accumulators --------------------------------
__global__ void k_zero() {
    int t = threadIdx.x;
    if (t < 2)   d_nsum[t] = 0.0;
    if (t < H1N) { d_s1[t] = 0.0; d_q1[t] = 0.0; d_s3[t] = 0.0; d_q3[t] = 0.0; }
    if (t < H2N) { d_s2[t] = 0.0; d_q2[t] = 0.0; }
}

// ---------------- K1: per-row sums of x ------------------------------------
__global__ __launch_bounds__(256) void k_rowsum(const float* __restrict__ x) {
    int b = blockIdx.x;
    const float4* row = (const float4*)(x + (size_t)b * D_COLS);
    float s = 0.f;
#pragma unroll
    for (int i = 0; i < 4; i++) {
        float4 v = row[threadIdx.x + i * 256];
        s += (v.x + v.y) + (v.z + v.w);
    }
#pragma unroll
    for (int o = 16; o > 0; o >>= 1) s += __shfl_down_sync(0xffffffffu, s, o);
    __shared__ float ws[8];
    if ((threadIdx.x & 31) == 0) ws[threadIdx.x >> 5] = s;
    __syncthreads();
    if (threadIdx.x == 0) {
        float t = 0.f;
#pragma unroll
        for (int i = 0; i < 8; i++) t += ws[i];
        d_srow[b] = t;
    }
}

// ---------------- K2: lower median via 32-pass radix select ----------------
__global__ void k_median() {
    extern __shared__ u32 keys[];
    __shared__ int cnt;
    int tid = threadIdx.x;
    for (int i = tid; i < B_ROWS; i += 1024) {
        u32 u = __float_as_uint(d_srow[i]);
        keys[i] = (u & 0x80000000u) ? ~u : (u | 0x80000000u);
    }
    __syncthreads();

    u32 prefix = 0;
    int k = (B_ROWS - 1) / 2;
    for (int bit = 31; bit >= 0; --bit) {
        u32 bmask = 1u << bit;
        u32 hmask = ~((bmask << 1) - 1u);
        if (tid == 0) cnt = 0;
        __syncthreads();
        int local = 0;
        for (int i = tid; i < B_ROWS; i += 1024) {
            u32 kv = keys[i];
            if ((((kv ^ prefix) & hmask) == 0) && !(kv & bmask)) local++;
        }
        atomicAdd(&cnt, local);
        __syncthreads();
        int c0 = cnt;
        if (k >= c0) { prefix |= bmask; k -= c0; }
        __syncthreads();
    }
    if (tid == 0) {
        u32 u = (prefix & 0x80000000u) ? (prefix & 0x7FFFFFFFu) : ~prefix;
        d_med = __uint_as_float(u);
    }
}

// ---------------- K3: fused norm + GEMM1 (3xBF16 k16, K-split, pipelined) --
// grid (256, 4). 256 thr = 8 warps: 4(M)x2(N). A: [row][half-k] bf16x2,
// stride 20. W: transposed [col][half-k] bf16x2, stride 20 (conflict-free
// for the (g,t) fragment pattern proven in k_out).
#define G1_ALD 20
#define G1_WLD 20
__global__ __launch_bounds__(256) void k_gemm1(const float* __restrict__ x,
                                               const float* __restrict__ Win) {
    __shared__ float rfac[64];
    __shared__ u32 Ahi[64 * G1_ALD], Alo[64 * G1_ALD];   // [row][kh]
    __shared__ u32 Whi[64 * G1_WLD], Wlo[64 * G1_WLD];   // [col][kh]
    __shared__ double red[512];
    int tid = threadIdx.x;
    int r0  = blockIdx.x * 64;
    int kb  = blockIdx.y * KSLAB;
    if (tid < 64) rfac[tid] = d_med / d_srow[r0 + tid];
    __syncthreads();

    int warp = tid >> 5, lane = tid & 31;
    int wm = warp >> 1, wn = warp & 1;
    int g = lane >> 2, t = lane & 3;
    int lrow = tid >> 2, lk = (tid & 3) * 8;     // A loader: 4 thr/row, 8 k each
    int wkrp = tid >> 4, wcolq = (tid & 15) * 4; // W loader: k-pair 0..15, 4 cols
    float rf = rfac[lrow];

    const float* xp = x + (size_t)(r0 + lrow) * D_COLS + kb + lk;
    const float* wp = Win + (size_t)(kb + 2 * wkrp) * 64 + wcolq;

    float cfr[4][4];
#pragma unroll
    for (int nt = 0; nt < 4; nt++)
#pragma unroll
        for (int i = 0; i < 4; i++) cfr[nt][i] = 0.f;
    double dsum = 0.0, dsq = 0.0;

    // prefetch chunk 0
    float4 xv0 = *(const float4*)(xp);
    float4 xv1 = *(const float4*)(xp + 4);
    float4 wva = *(const float4*)(wp);        // k row 2*wkrp
    float4 wvb = *(const float4*)(wp + 64);   // k row 2*wkrp+1

    const int NCH = KSLAB / 32;
    for (int c = 0; c < NCH; c++) {
        // ---- compute from regs: norm + bf16 split + stats ----
        float n[8] = {
            __logf(fmaf(xv0.x, rf, 1.f)), __logf(fmaf(xv0.y, rf, 1.f)),
            __logf(fmaf(xv0.z, rf, 1.f)), __logf(fmaf(xv0.w, rf, 1.f)),
            __logf(fmaf(xv1.x, rf, 1.f)), __logf(fmaf(xv1.y, rf, 1.f)),
            __logf(fmaf(xv1.z, rf, 1.f)), __logf(fmaf(xv1.w, rf, 1.f)) };
        us16 nh[8], nl[8];
        float ls = 0.f, lq = 0.f;
#pragma unroll
        for (int j = 0; j < 8; j++) {
            ls += n[j]; lq = fmaf(n[j], n[j], lq);
            bf_split(n[j], nh[j], nl[j]);
        }
        dsum += (double)ls; dsq += (double)lq;
        float wa[4] = {wva.x, wva.y, wva.z, wva.w};
        float wb[4] = {wvb.x, wvb.y, wvb.z, wvb.w};
        us16 wah[4], wal[4], wbh[4], wbl[4];
#pragma unroll
        for (int j = 0; j < 4; j++) {
            bf_split(wa[j], wah[j], wal[j]);
            bf_split(wb[j], wbh[j], wbl[j]);
        }

        __syncthreads();   // previous mma done reading smem
        {
            u32* ah = Ahi + lrow * G1_ALD + (lk >> 1);
            u32* al = Alo + lrow * G1_ALD + (lk >> 1);
            *(uint4*)(ah) = make_uint4(pack_us(nh[0], nh[1]), pack_us(nh[2], nh[3]),
                                       pack_us(nh[4], nh[5]), pack_us(nh[6], nh[7]));
            *(uint4*)(al) = make_uint4(pack_us(nl[0], nl[1]), pack_us(nl[2], nl[3]),
                                       pack_us(nl[4], nl[5]), pack_us(nl[6], nl[7]));
#pragma unroll
            for (int j = 0; j < 4; j++) {
                int col = wcolq + j;
                Whi[col * G1_WLD + wkrp] = pack_us(wah[j], wbh[j]);
                Wlo[col * G1_WLD + wkrp] = pack_us(wal[j], wbl[j]);
            }
        }
        // ---- issue next chunk's loads (hidden under mma phase) ----
        if (c + 1 < NCH) {
            const float* xn = xp + (c + 1) * 32;
            const float* wn = wp + (size_t)(c + 1) * 32 * 64;
            xv0 = *(const float4*)(xn);
            xv1 = *(const float4*)(xn + 4);
            wva = *(const float4*)(wn);
            wvb = *(const float4*)(wn + 64);
        }
        __syncthreads();   // smem tiles visible

        // ---- mma: 2 k-steps of 16 ----
        int arow0 = wm * 16 + g;
#pragma unroll
        for (int kt = 0; kt < 2; kt++) {
            int k0h = kt * 8;
            u32 ah[4], al[4];
            ah[0] = Ahi[arow0 * G1_ALD + k0h + t];
            ah[1] = Ahi[(arow0 + 8) * G1_ALD + k0h + t];
            ah[2] = Ahi[arow0 * G1_ALD + k0h + t + 4];
            ah[3] = Ahi[(arow0 + 8) * G1_ALD + k0h + t + 4];
            al[0] = Alo[arow0 * G1_ALD + k0h + t];
            al[1] = Alo[(arow0 + 8) * G1_ALD + k0h + t];
            al[2] = Alo[arow0 * G1_ALD + k0h + t + 4];
            al[3] = Alo[(arow0 + 8) * G1_ALD + k0h + t + 4];
#pragma unroll
            for (int nt = 0; nt < 4; nt++) {
                int bc = wn * 32 + nt * 8 + g;
                u32 bh[2] = { Whi[bc * G1_WLD + k0h + t], Whi[bc * G1_WLD + k0h + t + 4] };
                u32 bl[2] = { Wlo[bc * G1_WLD + k0h + t], Wlo[bc * G1_WLD + k0h + t + 4] };
                mma16816bf(cfr[nt], ah, bh);
                mma16816bf(cfr[nt], al, bh);
                mma16816bf(cfr[nt], ah, bl);
            }
        }
    }
    // ---- writeback partial G for this slab ----
    size_t gbase = (size_t)blockIdx.y * B_ROWS * 64;
#pragma unroll
    for (int nt = 0; nt < 4; nt++) {
        int col = wn * 32 + nt * 8 + t * 2;
        int rA = r0 + wm * 16 + g, rB = rA + 8;
        *(float2*)&d_Gp[gbase + (size_t)rA * 64 + col] = make_float2(cfr[nt][0], cfr[nt][1]);
        *(float2*)&d_Gp[gbase + (size_t)rB * 64 + col] = make_float2(cfr[nt][2], cfr[nt][3]);
    }
    // ---- global norm stats reduction ----
    red[tid] = dsum; red[256 + tid] = dsq;
    __syncthreads();
    for (int s = 128; s > 0; s >>= 1) {
        if (tid < s) { red[tid] += red[tid + s]; red[256 + tid] += red[256 + tid + s]; }
        __syncthreads();
    }
    if (tid == 0) {
        atomicAdd(&d_nsum[0], red[0]);
        atomicAdd(&d_nsum[1], red[256]);
    }
}

// ---------------- K4: reduce G slabs + column stats ------------------------
__global__ __launch_bounds__(256) void k_colstatsG() {
    int col = threadIdx.x & 63, rg = threadIdx.x >> 6;
    int r0 = blockIdx.x * 256;
    double s = 0.0, q = 0.0;
    const size_t SL = (size_t)B_ROWS * 64;
    for (int r = rg; r < 256; r += 4) {
        size_t idx = (size_t)(r0 + r) * 64 + col;
        float v = (d_Gp[idx] + d_Gp[SL + idx]) + (d_Gp[2 * SL + idx] + d_Gp[3 * SL + idx]);
        d_G[idx] = v;
        s += (double)v; q += (double)v * (double)v;
    }
    __shared__ double sh[256], shq[256];
    sh[threadIdx.x] = s; shq[threadIdx.x] = q;
    __syncthreads();
    if (rg == 0) {
#pragma unroll
        for (int g = 1; g < 4; g++) { s += sh[col + 64 * g]; q += shq[col + 64 * g]; }
        atomicAdd(&d_s1[col], s);
        atomicAdd(&d_q1[col], q);
    }
}

// ---------------- K5: layer-1 BN+ReLU -> h1 @ W_enc + b_enc (+stats) -------
__global__ __launch_bounds__(256) void k_mlp2(const float* __restrict__ g1,
                                              const float* __restrict__ bt1,
                                              const float* __restrict__ Wenc,
                                              const float* __restrict__ benc) {
    __shared__ float mu1[64], sc1[64], bts[64];
    __shared__ float We[64 * 32];
    __shared__ float be[32];
    __shared__ float h1buf[8][64];
    int tid = threadIdx.x;
    if (tid < 64) {
        double tot = d_nsum[0], totq = d_nsum[1];
        double sigma2 = (totq - tot * tot / BD_TOT) / (BD_TOT - 1.0);
        double mu  = d_s1[tid] / 16384.0;
        double var = d_q1[tid] / 16384.0 - mu * mu;
        mu1[tid] = (float)mu;
        sc1[tid] = g1[tid] * (float)rsqrt(var + 1e-5 * sigma2);
        bts[tid] = bt1[tid];
    }
    for (int i = tid; i < 64 * 32; i += 256) We[i] = Wenc[i];
    if (tid < 32) be[tid] = benc[tid];
    __syncthreads();

    int w = tid >> 5, lane = tid & 31;
    int rbase = blockIdx.x * 64 + w * 8;
    float ls = 0.f, lq = 0.f;
    for (int rr = 0; rr < 8; rr++) {
        int row = rbase + rr;
        float a0 = d_G[(size_t)row * 64 + lane];
        float a1 = d_G[(size_t)row * 64 + 32 + lane];
        h1buf[w][lane]      = fmaxf(fmaf(a0 - mu1[lane],      sc1[lane],      bts[lane]),      0.f);
        h1buf[w][32 + lane] = fmaxf(fmaf(a1 - mu1[32 + lane], sc1[32 + lane], bts[32 + lane]), 0.f);
        __syncwarp();
        float acc = be[lane];
#pragma unroll
        for (int k = 0; k < 64; k++) acc = fmaf(h1buf[w][k], We[k * 32 + lane], acc);
        d_H2[(size_t)row * 32 + lane] = acc;
        ls += acc; lq += acc * acc;
        __syncwarp();
    }
    atomicAdd(&d_s2[lane], (double)ls);
    atomicAdd(&d_q2[lane], (double)lq);
}

// ---------------- K6: layer-2 BN+ReLU -> h2 @ W_dec + b_dec (+stats) -------
__global__ __launch_bounds__(256) void k_mlp3(const float* __restrict__ g2,
                                              const float* __restrict__ bt2,
                                              const float* __restrict__ Wdec,
                                              const float* __restrict__ bdec) {
    __shared__ float mu2[32], sc2[32], bts[32];
    __shared__ float Wd[32 * 64];
    __shared__ float bd[64];
    __shared__ float h2buf[8][32];
    int tid = threadIdx.x;
    if (tid < 32) {
        double mu  = d_s2[tid] / 16384.0;
        double var = d_q2[tid] / 16384.0 - mu * mu;
        mu2[tid] = (float)mu;
        sc2[tid] = g2[tid] * (float)rsqrt(var + 1e-5);
        bts[tid] = bt2[tid];
    }
    for (int i = tid; i < 32 * 64; i += 256) Wd[i] = Wdec[i];
    if (tid < 64) bd[tid] = bdec[tid];
    __syncthreads();

    int w = tid >> 5, lane = tid & 31;
    int rbase = blockIdx.x * 64 + w * 8;
    float ls0 = 0.f, lq0 = 0.f, ls1 = 0.f, lq1 = 0.f;
    for (int rr = 0; rr < 8; rr++) {
        int row = rbase + rr;
        float v = d_H2[(size_t)row * 32 + lane];
        h2buf[w][lane] = fmaxf(fmaf(v - mu2[lane], sc2[lane], bts[lane]), 0.f);
        __syncwarp();
        float acc0 = bd[lane], acc1 = bd[32 + lane];
#pragma unroll
        for (int k = 0; k < 32; k++) {
            float h = h2buf[w][k];
            acc0 = fmaf(h, Wd[k * 64 + lane],      acc0);
            acc1 = fmaf(h, Wd[k * 64 + 32 + lane], acc1);
        }
        d_H3[(size_t)row * 64 + lane]      = acc0;
        d_H3[(size_t)row * 64 + 32 + lane] = acc1;
        ls0 += acc0; lq0 += acc0 * acc0;
        ls1 += acc1; lq1 += acc1 * acc1;
        __syncwarp();
    }
    atomicAdd(&d_s3[lane],      (double)ls0);
    atomicAdd(&d_q3[lane],      (double)lq0);
    atomicAdd(&d_s3[32 + lane], (double)ls1);
    atomicAdd(&d_q3[32 + lane], (double)lq1);
}

// ---------------- K7: BN3+ReLU -> h3 @ {W_pi,W_m,W_th} + act (bf16 MMA) ----
#define AH32 36
#define WS32 36
__global__ __launch_bounds__(256, 2) void k_out(const float* __restrict__ g3,
                                                const float* __restrict__ bt3,
                                                const float* __restrict__ Wpi,
                                                const float* __restrict__ bpi,
                                                const float* __restrict__ Wm,
                                                const float* __restrict__ bm,
                                                const float* __restrict__ Wth,
                                                const float* __restrict__ bth,
                                                float* __restrict__ out) {
    extern __shared__ u32 smu[];
    u32*   Ah  = smu;                        // 128 rows x 36 (32 halves + pad)
    u32*   Wsm = smu + 128 * AH32;           // 128 cols x 36 (32 halves + pad)
    float* mu3 = (float*)(smu + 128 * AH32 + 128 * WS32);
    float* sc3 = mu3 + 64;
    float* bts = sc3 + 64;
    float* bs  = bts + 64;                   // 128

    int tid = threadIdx.x;
    int mz  = blockIdx.z;
    const float* W  = (mz == 0) ? Wpi : ((mz == 1) ? Wm : Wth);
    const float* bb = (mz == 0) ? bpi : ((mz == 1) ? bm : bth);
    int c0 = blockIdx.x * 128, r0 = blockIdx.y * 128;

    if (tid < 64) {
        double mu  = d_s3[tid] / 16384.0;
        double var = d_q3[tid] / 16384.0 - mu * mu;
        mu3[tid] = (float)mu;
        sc3[tid] = g3[tid] * (float)rsqrt(var + 1e-5);
        bts[tid] = bt3[tid];
    }
    if (tid < 128) bs[tid] = bb[c0 + tid];
    __syncthreads();

    {   // ---- A tile: 128x64, BN+ReLU, pack bf16x2 ----
        int lr = tid >> 1, cb = (tid & 1) * 32, hb = (tid & 1) * 16;
        const float4* src = (const float4*)&d_H3[(size_t)(r0 + lr) * 64 + cb];
        u32* dst = Ah + lr * AH32 + hb;
#pragma unroll
        for (int j = 0; j < 8; j++) {
            float4 v = src[j];
            int c = cb + j * 4;
            float e0 = fmaxf(fmaf(v.x - mu3[c + 0], sc3[c + 0], bts[c + 0]), 0.f);
            float e1 = fmaxf(fmaf(v.y - mu3[c + 1], sc3[c + 1], bts[c + 1]), 0.f);
            float e2 = fmaxf(fmaf(v.z - mu3[c + 2], sc3[c + 2], bts[c + 2]), 0.f);
            float e3 = fmaxf(fmaf(v.w - mu3[c + 3], sc3[c + 3], bts[c + 3]), 0.f);
            *(uint2*)(dst + j * 2) = make_uint2(pack_bf16(e0, e1), pack_bf16(e2, e3));
        }
        // ---- W tile: 64k x 128col -> transposed bf16x2, permuted cols ----
#pragma unroll
        for (int it = 0; it < 4; it++) {
            int task = tid + it * 256;
            int krp  = task >> 5;            // 0..31 (k half-index)
            int colq = (task & 31) * 4;      // col group of 4
            const float* w0 = W + (size_t)(krp * 2) * 4096 + c0 + colq;
            float4 va = *(const float4*)(w0);
            float4 vb = *(const float4*)(w0 + 4096);
            int grp = colq >> 4, q = (colq & 15) >> 2;
            u32* base = Wsm + (grp * 16) * WS32 + krp;
            base[(2 * q)     * WS32] = pack_bf16(va.x, vb.x);
            base[(2 * q + 1) * WS32] = pack_bf16(va.y, vb.y);
            base[(8 + 2 * q)     * WS32] = pack_bf16(va.z, vb.z);
            base[(8 + 2 * q + 1) * WS32] = pack_bf16(va.w, vb.w);
        }
    }
    __syncthreads();

    int warp = tid >> 5, lane = tid & 31;
    int wm = warp >> 1, wn = warp & 1;
    int g = lane >> 2, t = lane & 3;
    int arow0 = wm * 32 + g;
    int bcol0 = wn * 64 + g;

    float cfr[2][8][4];
#pragma unroll
    for (int mt = 0; mt < 2; mt++)
#pragma unroll
        for (int nt = 0; nt < 8; nt++)
#pragma unroll
            for (int i = 0; i < 4; i++) cfr[mt][nt][i] = 0.f;

#pragma unroll
    for (int kt = 0; kt < 4; kt++) {         // K=64 in 4 steps of 16
        int k0h = kt * 8;
        u32 bfr[8][2];
#pragma unroll
        for (int nt = 0; nt < 8; nt++) {
            int col = bcol0 + nt * 8;
            bfr[nt][0] = Wsm[col * WS32 + k0h + t];
            bfr[nt][1] = Wsm[col * WS32 + k0h + t + 4];
        }
        u32 afr[2][4];
#pragma unroll
        for (int mt = 0; mt < 2; mt++) {
            int r = arow0 + mt * 16;
            afr[mt][0] = Ah[r * AH32 + k0h + t];
            afr[mt][1] = Ah[(r + 8) * AH32 + k0h + t];
            afr[mt][2] = Ah[r * AH32 + k0h + t + 4];
            afr[mt][3] = Ah[(r + 8) * AH32 + k0h + t + 4];
        }
#pragma unroll
        for (int mt = 0; mt < 2; mt++)
#pragma unroll
            for (int nt = 0; nt < 8; nt++)
                mma16816bf(cfr[mt][nt], afr[mt], bfr[nt]);
    }

    size_t obase = (size_t)mz * (size_t)B_ROWS * D_COLS + (size_t)r0 * D_COLS + c0;
#pragma unroll
    for (int mt = 0; mt < 2; mt++) {
        int rA = wm * 32 + mt * 16 + g;
        int rB = rA + 8;
#pragma unroll
        for (int p = 0; p < 4; p++) {
            int gcb = wn * 64 + p * 16 + t * 4;
            float4 bv = *(float4*)&bs[gcb];
            float4 zA = make_float4(cfr[mt][2 * p][0] + bv.x, cfr[mt][2 * p][1] + bv.y,
                                    cfr[mt][2 * p + 1][0] + bv.z, cfr[mt][2 * p + 1][1] + bv.w);
            float4 zB = make_float4(cfr[mt][2 * p][2] + bv.x, cfr[mt][2 * p][3] + bv.y,
                                    cfr[mt][2 * p + 1][2] + bv.z, cfr[mt][2 * p + 1][3] + bv.w);
            if (mz == 0) {
                zA.x = fast_sigmoid(zA.x); zA.y = fast_sigmoid(zA.y);
                zA.z = fast_sigmoid(zA.z); zA.w = fast_sigmoid(zA.w);
                zB.x = fast_sigmoid(zB.x); zB.y = fast_sigmoid(zB.y);
                zB.z = fast_sigmoid(zB.z); zB.w = fast_sigmoid(zB.w);
            } else {
                zA.x = __expf(zA.x); zA.y = __expf(zA.y);
                zA.z = __expf(zA.z); zA.w = __expf(zA.w);
                zB.x = __expf(zB.x); zB.y = __expf(zB.y);
                zB.z = __expf(zB.z); zB.w = __expf(zB.w);
            }
            *(float4*)&out[obase + (size_t)rA * D_COLS + gcb] = zA;
            *(float4*)&out[obase + (size_t)rB * D_COLS + gcb] = zB;
        }
    }
}

// ---------------- launch ----------------------------------------------------
extern "C" void kernel_launch(void* const* d_in, const int* in_sizes, int n_in,
                              void* d_out, int out_size) {
    const float* x    = (const float*)d_in[0];
    const float* Win  = (const float*)d_in[1];
    const float* g1   = (const float*)d_in[3];
    const float* bt1  = (const float*)d_in[4];
    const float* Wenc = (const float*)d_in[5];
    const float* benc = (const float*)d_in[6];
    const float* g2   = (const float*)d_in[7];
    const float* bt2  = (const float*)d_in[8];
    const float* Wdec = (const float*)d_in[9];
    const float* bdec = (const float*)d_in[10];
    const float* g3   = (const float*)d_in[11];
    const float* bt3  = (const float*)d_in[12];
    const float* Wpi  = (const float*)d_in[13];
    const float* bpi  = (const float*)d_in[14];
    const float* Wm   = (const float*)d_in[15];
    const float* bm   = (const float*)d_in[16];
    const float* Wth  = (const float*)d_in[17];
    const float* bth  = (const float*)d_in[18];
    float* out = (float*)d_out;

    const int koutSmem = (128 * AH32 + 128 * WS32) * 4 + (64 * 3 + 128) * 4;

    cudaFuncSetAttribute(k_median, cudaFuncAttributeMaxDynamicSharedMemorySize, 65536);
    cudaFuncSetAttribute(k_out,    cudaFuncAttributeMaxDynamicSharedMemorySize, koutSmem);

    k_zero<<<1, 64>>>();
    k_rowsum<<<B_ROWS, 256>>>(x);
    k_median<<<1, 1024, 65536>>>();
    dim3 g1grid(B_ROWS / 64, NSLAB);
    k_gemm1<<<g1grid, 256>>>(x, Win);
    k_colstatsG<<<64, 256>>>();
    k_mlp2<<<B_ROWS / 64, 256>>>(g1, bt1, Wenc, benc);
    k_mlp3<<<B_ROWS / 64, 256>>>(g2, bt2, Wdec, bdec);
    dim3 g(D_COLS / 128, B_ROWS / 128, 3);
    k_out<<<g, 256, koutSmem>>>(g3, bt3, Wpi, bpi, Wm, bm, Wth, bth, out);
}